// round 9
// baseline (speedup 1.0000x reference)
#include <cuda_runtime.h>
#include <cuda_bf16.h>
#include <cstdint>

// Problem constants
#define BB 4
#define SS 2048
#define DD 1024
#define MM (BB*SS)       // 8192
#define K3 (3*DD)        // 3072  (split-tripled K for projections/scores)
#define S3 (3*SS)        // 6144  (split-tripled K for PV)

// GEMM tiling: CTA 128x256, warp tile 64x64 (8 warps = 2 x 4)
#define TM 128
#define TN 256
#define TK 64
#define AST 72           // TK + 8 pad: 144B row stride, ldmatrix conflict-free
#define ST 3             // cp.async stages

#define A_ELEMS (TM*AST)                       // 9216 elems
#define B_ELEMS (TN*AST)                       // 18432 elems
#define STAGE_ELEMS (A_ELEMS + B_ELEMS)        // 27648 elems
#define DYN_BYTES (ST*STAGE_ELEMS*2)           // 165888 B dynamic smem (1 CTA/SM)

// ---------------------------------------------------------------------------
// Scratch (__device__ globals).  A-type row = [hi|lo|hi], B-type = [hi|hi|lo]:
// plain bf16 GEMM over tripled K computes hi*hi + lo*hi + hi*lo.
// ---------------------------------------------------------------------------
__device__ __nv_bfloat16 g_xs[(size_t)MM * K3];
__device__ __nv_bfloat16 g_wq[(size_t)DD * K3];
__device__ __nv_bfloat16 g_wk[(size_t)DD * K3];
__device__ __nv_bfloat16 g_wv[(size_t)DD * K3];
__device__ __nv_bfloat16 g_qs[(size_t)MM * K3];
__device__ __nv_bfloat16 g_ks[(size_t)MM * K3];
__device__ __nv_bfloat16 g_vt[(size_t)BB * DD * S3];
__device__ float         g_sc[(size_t)BB * SS * SS];
__device__ __nv_bfloat16 g_ps[(size_t)BB * SS * S3];

__device__ __forceinline__ void split2(float v, __nv_bfloat16& h, __nv_bfloat16& l) {
    h = __float2bfloat16(v);
    l = __float2bfloat16(v - __bfloat162float(h));
}

// ---------------------------------------------------------------------------
// Split input kernels
// ---------------------------------------------------------------------------
__global__ __launch_bounds__(256) void split_x_kernel(const float* __restrict__ x)
{
    size_t idx = (size_t)blockIdx.x * 256 + threadIdx.x;
    size_t m = idx >> 10, d = idx & (DD - 1);
    __nv_bfloat16 h, l;
    split2(x[idx], h, l);
    __nv_bfloat16* r = g_xs + m * K3;
    r[d] = h; r[DD + d] = l; r[2 * DD + d] = h;            // A-type
}

__global__ __launch_bounds__(256) void split_w_kernel(
    const float* __restrict__ Wq, const float* __restrict__ Wk,
    const float* __restrict__ Wv)
{
    int z = blockIdx.z;
    size_t idx = (size_t)blockIdx.x * 256 + threadIdx.x;
    const float* W = (z == 0) ? Wq : (z == 1) ? Wk : Wv;
    __nv_bfloat16* O = (z == 0) ? g_wq : (z == 1) ? g_wk : g_wv;
    size_t e = idx >> 10, d = idx & (DD - 1);
    __nv_bfloat16 h, l;
    split2(W[idx], h, l);
    __nv_bfloat16* r = O + e * K3;
    r[d] = h; r[DD + d] = h; r[2 * DD + d] = l;            // B-type
}

// ---------------------------------------------------------------------------
// GEMM core: C[128x256] = A[row0..][.] * B[col0..][.]^T, bf16 K-major.
// Warp tile 64x64.  3-stage cp.async ring; register fragment pipeline
// carried across tile boundaries (k0 of tile t+1 preloaded during k3 of t).
// Requires ntiles >= 3 (all call sites have ntiles >= 6).
// ---------------------------------------------------------------------------
struct KLin {
    __device__ __forceinline__ int operator()(int t) const { return t * TK; }
};
struct KSeg {
    int tps;  // tiles per segment
    __device__ __forceinline__ int operator()(int t) const {
        int s = t / tps; return s * SS + (t - s * tps) * TK;
    }
};

#define LDSM_X4(r0, r1, r2, r3, addr) \
    asm volatile("ldmatrix.sync.aligned.m8n8.x4.shared.b16 {%0,%1,%2,%3}, [%4];" \
                 : "=r"(r0), "=r"(r1), "=r"(r2), "=r"(r3) : "r"(addr))

#define MMA16816(c, a, b0, b1)                                                \
    asm volatile(                                                             \
        "mma.sync.aligned.m16n8k16.row.col.f32.bf16.bf16.f32 "                \
        "{%0,%1,%2,%3}, {%4,%5,%6,%7}, {%8,%9}, {%0,%1,%2,%3};\n"             \
        : "+f"((c)[0]), "+f"((c)[1]), "+f"((c)[2]), "+f"((c)[3])              \
        : "r"((a)[0]), "r"((a)[1]), "r"((a)[2]), "r"((a)[3]), "r"(b0), "r"(b1))

template <typename KF>
__device__ __forceinline__ void gemm_core(
    const __nv_bfloat16* __restrict__ A, int row0, size_t lda,
    const __nv_bfloat16* __restrict__ B, int col0, size_t ldb,
    int ntiles, KF koff, float acc[4][8][4])
{
    extern __shared__ __align__(16) __nv_bfloat16 smem[];

    const int tid  = threadIdx.x;
    const int lane = tid & 31, warp = tid >> 5;
    const int wm = (warp & 1) << 6;       // 0/64
    const int wn = (warp >> 1) << 6;      // 0/64/128/192
    const int lr  = lane & 7;
    const int seg = lane >> 3;            // 0..3
    const int lrow = tid >> 3;            // loader row base 0..31
    const int lcol = (tid & 7) << 3;      // loader elem col 0..56

    // ldmatrix lane-address bases (bytes) per pipeline stage
    uint32_t aBase[ST], bBase[ST];
#pragma unroll
    for (int s = 0; s < ST; s++) {
        aBase[s] = (uint32_t)__cvta_generic_to_shared(
            smem + s * STAGE_ELEMS + (wm + ((seg & 1) << 3) + lr) * AST + ((seg >> 1) << 3));
        bBase[s] = (uint32_t)__cvta_generic_to_shared(
            smem + s * STAGE_ELEMS + A_ELEMS + (wn + ((seg >> 1) << 3) + lr) * AST + ((seg & 1) << 3));
    }

    auto LDT = [&](int t) {
        const int ko = koff(t);
        __nv_bfloat16* as = smem + (t % ST) * STAGE_ELEMS;
        __nv_bfloat16* bs = as + A_ELEMS;
#pragma unroll
        for (int i = 0; i < 4; i++) {      // A: 128 rows
            const int r = lrow + (i << 5);
            const void* sa = (const void*)(A + (size_t)(row0 + r) * lda + ko + lcol);
            uint32_t da = (uint32_t)__cvta_generic_to_shared(&as[r * AST + lcol]);
            asm volatile("cp.async.cg.shared.global [%0], [%1], 16;" :: "r"(da), "l"(sa));
        }
#pragma unroll
        for (int i = 0; i < 8; i++) {      // B: 256 rows
            const int r = lrow + (i << 5);
            const void* sb = (const void*)(B + (size_t)(col0 + r) * ldb + ko + lcol);
            uint32_t db = (uint32_t)__cvta_generic_to_shared(&bs[r * AST + lcol]);
            asm volatile("cp.async.cg.shared.global [%0], [%1], 16;" :: "r"(db), "l"(sb));
        }
        asm volatile("cp.async.commit_group;" ::: "memory");
    };

    // Prologue: fill all 3 stages, arm k0 fragments of tile 0.
    LDT(0); LDT(1); LDT(2);
    asm volatile("cp.async.wait_group 2;" ::: "memory");
    __syncthreads();

    uint32_t af[2][4][4], bf[2][4][4];
#pragma unroll
    for (int mi = 0; mi < 4; mi++)
        LDSM_X4(af[0][mi][0], af[0][mi][1], af[0][mi][2], af[0][mi][3],
                aBase[0] + mi * (16 * AST * 2));
#pragma unroll
    for (int n2 = 0; n2 < 4; n2++)
        LDSM_X4(bf[0][n2][0], bf[0][n2][1], bf[0][n2][2], bf[0][n2][3],
                bBase[0] + n2 * (16 * AST * 2));

    for (int t = 0; t < ntiles; t++) {
        const int st = t % ST;
        const uint32_t ab = aBase[st], bb = bBase[st];

        // k-steps 0..2: prefetch next k-step fragments, mma current
#pragma unroll
        for (int kk = 0; kk < 3; kk++) {
            const int cur = kk & 1, nxt = cur ^ 1;
            const uint32_t ak = ab + (kk + 1) * 32;
            const uint32_t bk = bb + (kk + 1) * 32;
#pragma unroll
            for (int mi = 0; mi < 4; mi++)
                LDSM_X4(af[nxt][mi][0], af[nxt][mi][1], af[nxt][mi][2], af[nxt][mi][3],
                        ak + mi * (16 * AST * 2));
#pragma unroll
            for (int n2 = 0; n2 < 4; n2++)
                LDSM_X4(bf[nxt][n2][0], bf[nxt][n2][1], bf[nxt][n2][2], bf[nxt][n2][3],
                        bk + n2 * (16 * AST * 2));
#pragma unroll
            for (int mi = 0; mi < 4; mi++)
#pragma unroll
                for (int ni = 0; ni < 8; ni++)
                    MMA16816(acc[mi][ni], af[cur][mi],
                             bf[cur][ni >> 1][(ni & 1) << 1],
                             bf[cur][ni >> 1][((ni & 1) << 1) + 1]);
        }

        // k-step 3: publish stage t+1, preload its k0 fragments, then mma k3.
        if (t + 1 < ntiles) {
            if (t + 3 <= ntiles) { asm volatile("cp.async.wait_group 1;" ::: "memory"); }
            else                 { asm volatile("cp.async.wait_group 0;" ::: "memory"); }
            __syncthreads();                       // publish stage t+1; drain stage t reads
            const int sn = (t + 1) % ST;
#pragma unroll
            for (int mi = 0; mi < 4; mi++)
                LDSM_X4(af[0][mi][0], af[0][mi][1], af[0][mi][2], af[0][mi][3],
                        aBase[sn] + mi * (16 * AST * 2));
#pragma unroll
            for (int n2 = 0; n2 < 4; n2++)
                LDSM_X4(bf[0][n2][0], bf[0][n2][1], bf[0][n2][2], bf[0][n2][3],
                        bBase[sn] + n2 * (16 * AST * 2));
        }
#pragma unroll
        for (int mi = 0; mi < 4; mi++)
#pragma unroll
            for (int ni = 0; ni < 8; ni++)
                MMA16816(acc[mi][ni], af[1][mi],
                         bf[1][ni >> 1][(ni & 1) << 1],
                         bf[1][ni >> 1][((ni & 1) << 1) + 1]);

        if (t + 3 < ntiles) LDT(t + 3);            // refill stage just drained
    }
    __syncthreads();
}

// ---------------------------------------------------------------------------
// Kernel: QKV projections (z = 0/1/2 -> Q/K/V), epilogue writes bf16 splits.
// ---------------------------------------------------------------------------
__global__ __launch_bounds__(256) void proj_kernel(
    const float* __restrict__ bq, const float* __restrict__ bk,
    const float* __restrict__ bv)
{
    const int z = blockIdx.z;
    const __nv_bfloat16* W = (z == 0) ? g_wq : (z == 1) ? g_wk : g_wv;
    const float* bias      = (z == 0) ? bq   : (z == 1) ? bk   : bv;
    const int row0 = blockIdx.y * TM, col0 = blockIdx.x * TN;

    float acc[4][8][4];
#pragma unroll
    for (int i = 0; i < 4; i++)
#pragma unroll
        for (int j = 0; j < 8; j++)
#pragma unroll
            for (int q = 0; q < 4; q++) acc[i][j][q] = 0.f;

    gemm_core(g_xs, row0, K3, W, col0, K3, K3 / TK, KLin{}, acc);

    const int lane = threadIdx.x & 31, warp = threadIdx.x >> 5;
    const int wm = (warp & 1) << 6, wn = (warp >> 1) << 6;
    const int g = lane >> 2, tig = lane & 3;

#pragma unroll
    for (int mi = 0; mi < 4; mi++)
#pragma unroll
        for (int ni = 0; ni < 8; ni++) {
            const int n = col0 + wn + (ni << 3) + (tig << 1);
            const float b0 = bias[n], b1 = bias[n + 1];
#pragma unroll
            for (int rr = 0; rr < 2; rr++) {
                const int m = row0 + wm + (mi << 4) + g + rr * 8;
                float v0 = acc[mi][ni][rr * 2 + 0] + b0;
                float v1 = acc[mi][ni][rr * 2 + 1] + b1;
                __nv_bfloat16 h0, l0, h1, l1;
                split2(v0, h0, l0); split2(v1, h1, l1);
                if (z == 0) {          // Q: A-type [hi|lo|hi]
                    __nv_bfloat16* r = g_qs + (size_t)m * K3 + n;
                    __nv_bfloat162 th; th.x = h0; th.y = h1;
                    __nv_bfloat162 tl; tl.x = l0; tl.y = l1;
                    *(__nv_bfloat162*)(r)          = th;
                    *(__nv_bfloat162*)(r + DD)     = tl;
                    *(__nv_bfloat162*)(r + 2 * DD) = th;
                } else if (z == 1) {   // K: B-type [hi|hi|lo]
                    __nv_bfloat16* r = g_ks + (size_t)m * K3 + n;
                    __nv_bfloat162 th; th.x = h0; th.y = h1;
                    __nv_bfloat162 tl; tl.x = l0; tl.y = l1;
                    *(__nv_bfloat162*)(r)          = th;
                    *(__nv_bfloat162*)(r + DD)     = th;
                    *(__nv_bfloat162*)(r + 2 * DD) = tl;
                } else {               // V: transposed into g_vt[b][d][3S], B-type
                    const int b = m >> 11, s = m & (SS - 1);
                    __nv_bfloat16* r0 = g_vt + ((size_t)b * DD + n) * S3 + s;
                    r0[0] = h0; r0[SS] = h0; r0[2 * SS] = l0;
                    __nv_bfloat16* r1 = g_vt + ((size_t)b * DD + n + 1) * S3 + s;
                    r1[0] = h1; r1[SS] = h1; r1[2 * SS] = l1;
                }
            }
        }
}

// ---------------------------------------------------------------------------
// Kernel: scores = Q K^T / sqrt(D); tiles fully above the diagonal skipped.
// ---------------------------------------------------------------------------
__global__ __launch_bounds__(256) void scores_kernel()
{
    const int bx = blockIdx.x, by = blockIdx.y, b = blockIdx.z;
    const int row0 = by * TM, col0 = bx * TN;
    if (col0 > row0 + TM - 1) return;      // fully above causal diagonal
    const __nv_bfloat16* A  = g_qs + (size_t)b * SS * K3;
    const __nv_bfloat16* Bp = g_ks + (size_t)b * SS * K3;

    float acc[4][8][4];
#pragma unroll
    for (int i = 0; i < 4; i++)
#pragma unroll
        for (int j = 0; j < 8; j++)
#pragma unroll
            for (int q = 0; q < 4; q++) acc[i][j][q] = 0.f;

    gemm_core(A, row0, K3, Bp, col0, K3, K3 / TK, KLin{}, acc);

    float* C = g_sc + (size_t)b * SS * SS;
    const int lane = threadIdx.x & 31, warp = threadIdx.x >> 5;
    const int wm = (warp & 1) << 6, wn = (warp >> 1) << 6;
    const int g = lane >> 2, tig = lane & 3;

#pragma unroll
    for (int mi = 0; mi < 4; mi++)
#pragma unroll
        for (int ni = 0; ni < 8; ni++) {
            const int n = col0 + wn + (ni << 3) + (tig << 1);
#pragma unroll
            for (int rr = 0; rr < 2; rr++) {
                const int m = row0 + wm + (mi << 4) + g + rr * 8;
                float2 v;
                v.x = acc[mi][ni][rr * 2 + 0] * 0.03125f;
                v.y = acc[mi][ni][rr * 2 + 1] * 0.03125f;
                *(float2*)(C + (size_t)m * SS + n) = v;
            }
        }
}

// ---------------------------------------------------------------------------
// Kernel: causal row softmax; writes split weights (A-type) with zero fill.
// ---------------------------------------------------------------------------
__global__ __launch_bounds__(256) void softmax_kernel()
{
    const int row = blockIdx.x;
    const int b = row >> 11;
    const int i = row & (SS - 1);
    const float* p = g_sc + (size_t)b * SS * SS + (size_t)i * SS;
    __nv_bfloat16* o = g_ps + (size_t)b * SS * S3 + (size_t)i * S3;
    const int len = i + 1;
    const int tid = threadIdx.x;
    const int lane = tid & 31, wid = tid >> 5;
    __shared__ float red[8];

    float m = __int_as_float(0xff800000);
    float xv[8];
#pragma unroll
    for (int jj = 0; jj < 8; jj++) {
        int j = tid + jj * 256;
        xv[jj] = (j < len) ? p[j] : __int_as_float(0xff800000);
        m = fmaxf(m, xv[jj]);
    }
#pragma unroll
    for (int off = 16; off; off >>= 1) m = fmaxf(m, __shfl_xor_sync(0xffffffffu, m, off));
    if (lane == 0) red[wid] = m;
    __syncthreads();
    if (tid == 0) {
        float mm = red[0];
#pragma unroll
        for (int w = 1; w < 8; w++) mm = fmaxf(mm, red[w]);
        red[0] = mm;
    }
    __syncthreads();
    m = red[0];
    __syncthreads();

    float s = 0.f;
    float ev[8];
#pragma unroll
    for (int jj = 0; jj < 8; jj++) {
        int j = tid + jj * 256;
        ev[jj] = (j < len) ? __expf(xv[jj] - m) : 0.f;
        s += ev[jj];
    }
#pragma unroll
    for (int off = 16; off; off >>= 1) s += __shfl_xor_sync(0xffffffffu, s, off);
    if (lane == 0) red[wid] = s;
    __syncthreads();
    if (tid == 0) {
        float ss = 0.f;
#pragma unroll
        for (int w = 0; w < 8; w++) ss += red[w];
        red[0] = ss;
    }
    __syncthreads();
    const float inv = 1.f / red[0];

#pragma unroll
    for (int jj = 0; jj < 8; jj++) {
        int j = tid + jj * 256;
        float w = ev[jj] * inv;
        __nv_bfloat16 h, l;
        split2(w, h, l);
        o[j] = h; o[SS + j] = l; o[2 * SS + j] = h;        // A-type
    }
}

// ---------------------------------------------------------------------------
// Kernel: out = P V ; K runs 3 causal-capped segments (hi, lo, hi parts).
// ---------------------------------------------------------------------------
__global__ __launch_bounds__(256) void pv_kernel(float* __restrict__ out)
{
    const int bx = blockIdx.x, by = blockIdx.y, b = blockIdx.z;
    const __nv_bfloat16* A  = g_ps + (size_t)b * SS * S3;
    const __nv_bfloat16* Bp = g_vt + (size_t)b * DD * S3;
    const int row0 = by * TM, col0 = bx * TN;
    const int tps = (row0 + TM) / TK;      // causal cap per segment

    float acc[4][8][4];
#pragma unroll
    for (int i = 0; i < 4; i++)
#pragma unroll
        for (int j = 0; j < 8; j++)
#pragma unroll
            for (int q = 0; q < 4; q++) acc[i][j][q] = 0.f;

    gemm_core(A, row0, S3, Bp, col0, S3, 3 * tps, KSeg{tps}, acc);

    float* C = out + (size_t)b * SS * DD;
    const int lane = threadIdx.x & 31, warp = threadIdx.x >> 5;
    const int wm = (warp & 1) << 6, wn = (warp >> 1) << 6;
    const int g = lane >> 2, tig = lane & 3;

#pragma unroll
    for (int mi = 0; mi < 4; mi++)
#pragma unroll
        for (int ni = 0; ni < 8; ni++) {
            const int n = col0 + wn + (ni << 3) + (tig << 1);
#pragma unroll
            for (int rr = 0; rr < 2; rr++) {
                const int m = row0 + wm + (mi << 4) + g + rr * 8;
                float2 v;
                v.x = acc[mi][ni][rr * 2 + 0];
                v.y = acc[mi][ni][rr * 2 + 1];
                *(float2*)(C + (size_t)m * DD + n) = v;
            }
        }
}

// ---------------------------------------------------------------------------
extern "C" void kernel_launch(void* const* d_in, const int* in_sizes, int n_in,
                              void* d_out, int out_size)
{
    const float* x  = (const float*)d_in[0];
    const float* Wq = (const float*)d_in[1];
    const float* bq = (const float*)d_in[2];
    const float* Wk = (const float*)d_in[3];
    const float* bk = (const float*)d_in[4];
    const float* Wv = (const float*)d_in[5];
    const float* bv = (const float*)d_in[6];
    float* out = (float*)d_out;

    cudaFuncSetAttribute(proj_kernel,   cudaFuncAttributeMaxDynamicSharedMemorySize, DYN_BYTES);
    cudaFuncSetAttribute(scores_kernel, cudaFuncAttributeMaxDynamicSharedMemorySize, DYN_BYTES);
    cudaFuncSetAttribute(pv_kernel,     cudaFuncAttributeMaxDynamicSharedMemorySize, DYN_BYTES);

    split_x_kernel<<<(MM * DD) / 256, 256>>>(x);
    split_w_kernel<<<dim3((DD * DD) / 256, 1, 3), 256>>>(Wq, Wk, Wv);
    proj_kernel<<<dim3(DD / TN, MM / TM, 3), 256, DYN_BYTES>>>(bq, bk, bv);
    scores_kernel<<<dim3(SS / TN, SS / TM, BB), 256, DYN_BYTES>>>();
    softmax_kernel<<<BB * SS, 256>>>();
    pv_kernel<<<dim3(DD / TN, SS / TM, BB), 256, DYN_BYTES>>>(out);
}

// round 10
// speedup vs baseline: 1.6508x; 1.6508x over previous
#include <cuda_runtime.h>
#include <cuda_bf16.h>
#include <cstdint>

// Problem constants
#define BB 4
#define SS 2048
#define DD 1024
#define MM (BB*SS)       // 8192
#define K3 (3*DD)        // 3072  (split-tripled K for projections/scores)
#define S3 (3*SS)        // 6144  (split-tripled K for PV)

// GEMM tiling: CTA 128x128 with 4 warps (128 thr), warp tile 64x64
#define TM 128
#define TN 128
#define TK 64
#define AST 72           // TK + 8 pad: 144B row stride, ldmatrix conflict-free
#define ST 3             // cp.async stages (110.6KB -> 2 CTA/SM)

#define A_ELEMS (TM*AST)              // elems per A stage
#define STAGE_ELEMS (2*A_ELEMS)       // A + B
#define DYN_BYTES (ST*STAGE_ELEMS*2)  // 110592 B dynamic smem

// ---------------------------------------------------------------------------
// Scratch (__device__ globals).  A-type row = [hi|lo|hi], B-type = [hi|hi|lo]:
// plain bf16 GEMM over tripled K computes hi*hi + lo*hi + hi*lo.
// ---------------------------------------------------------------------------
__device__ __nv_bfloat16 g_xs[(size_t)MM * K3];
__device__ __nv_bfloat16 g_wq[(size_t)DD * K3];
__device__ __nv_bfloat16 g_wk[(size_t)DD * K3];
__device__ __nv_bfloat16 g_wv[(size_t)DD * K3];
__device__ __nv_bfloat16 g_qs[(size_t)MM * K3];
__device__ __nv_bfloat16 g_ks[(size_t)MM * K3];
__device__ __nv_bfloat16 g_vt[(size_t)BB * DD * S3];
__device__ float         g_sc[(size_t)BB * SS * SS];
__device__ __nv_bfloat16 g_ps[(size_t)BB * SS * S3];

__device__ __forceinline__ void split2(float v, __nv_bfloat16& h, __nv_bfloat16& l) {
    h = __float2bfloat16(v);
    l = __float2bfloat16(v - __bfloat162float(h));
}

// ---------------------------------------------------------------------------
// Split input kernels
// ---------------------------------------------------------------------------
__global__ __launch_bounds__(256) void split_x_kernel(const float* __restrict__ x)
{
    size_t idx = (size_t)blockIdx.x * 256 + threadIdx.x;
    size_t m = idx >> 10, d = idx & (DD - 1);
    __nv_bfloat16 h, l;
    split2(x[idx], h, l);
    __nv_bfloat16* r = g_xs + m * K3;
    r[d] = h; r[DD + d] = l; r[2 * DD + d] = h;            // A-type
}

__global__ __launch_bounds__(256) void split_w_kernel(
    const float* __restrict__ Wq, const float* __restrict__ Wk,
    const float* __restrict__ Wv)
{
    int z = blockIdx.z;
    size_t idx = (size_t)blockIdx.x * 256 + threadIdx.x;
    const float* W = (z == 0) ? Wq : (z == 1) ? Wk : Wv;
    __nv_bfloat16* O = (z == 0) ? g_wq : (z == 1) ? g_wk : g_wv;
    size_t e = idx >> 10, d = idx & (DD - 1);
    __nv_bfloat16 h, l;
    split2(W[idx], h, l);
    __nv_bfloat16* r = O + e * K3;
    r[d] = h; r[DD + d] = h; r[2 * DD + d] = l;            // B-type
}

// ---------------------------------------------------------------------------
// GEMM core: C[128x128] = A[row0..][.] * B[col0..][.]^T, bf16 K-major.
// 4 warps, warp tile 64x64.  3-stage cp.async ring; register fragment
// pipeline carried across tile boundaries (k0 of t+1 preloaded during k3
// of t).  Requires ntiles >= 3 (all call sites have ntiles >= 6).
// ---------------------------------------------------------------------------
struct KLin {
    __device__ __forceinline__ int operator()(int t) const { return t * TK; }
};
struct KSeg {
    int tps;  // tiles per segment
    __device__ __forceinline__ int operator()(int t) const {
        int s = t / tps; return s * SS + (t - s * tps) * TK;
    }
};

#define LDSM_X4(r0, r1, r2, r3, addr) \
    asm volatile("ldmatrix.sync.aligned.m8n8.x4.shared.b16 {%0,%1,%2,%3}, [%4];" \
                 : "=r"(r0), "=r"(r1), "=r"(r2), "=r"(r3) : "r"(addr))

#define MMA16816(c, a, b0, b1)                                                \
    asm volatile(                                                             \
        "mma.sync.aligned.m16n8k16.row.col.f32.bf16.bf16.f32 "                \
        "{%0,%1,%2,%3}, {%4,%5,%6,%7}, {%8,%9}, {%0,%1,%2,%3};\n"             \
        : "+f"((c)[0]), "+f"((c)[1]), "+f"((c)[2]), "+f"((c)[3])              \
        : "r"((a)[0]), "r"((a)[1]), "r"((a)[2]), "r"((a)[3]), "r"(b0), "r"(b1))

template <typename KF>
__device__ __forceinline__ void gemm_core(
    const __nv_bfloat16* __restrict__ A, int row0, size_t lda,
    const __nv_bfloat16* __restrict__ B, int col0, size_t ldb,
    int ntiles, KF koff, float acc[4][8][4])
{
    extern __shared__ __align__(16) __nv_bfloat16 smem[];

    const int tid  = threadIdx.x;
    const int lane = tid & 31, warp = tid >> 5;    // warp 0..3
    const int wm = (warp & 1) << 6;       // 0/64
    const int wn = (warp >> 1) << 6;      // 0/64
    const int lr  = lane & 7;
    const int seg = lane >> 3;            // 0..3
    const int lrow = tid >> 3;            // loader row base 0..15
    const int lcol = (tid & 7) << 3;      // loader elem col 0..56

    // ldmatrix lane-address bases (bytes) per pipeline stage
    uint32_t aBase[ST], bBase[ST];
#pragma unroll
    for (int s = 0; s < ST; s++) {
        aBase[s] = (uint32_t)__cvta_generic_to_shared(
            smem + s * STAGE_ELEMS + (wm + ((seg & 1) << 3) + lr) * AST + ((seg >> 1) << 3));
        bBase[s] = (uint32_t)__cvta_generic_to_shared(
            smem + s * STAGE_ELEMS + A_ELEMS + (wn + ((seg >> 1) << 3) + lr) * AST + ((seg & 1) << 3));
    }

    auto LDT = [&](int t) {
        const int ko = koff(t);
        __nv_bfloat16* as = smem + (t % ST) * STAGE_ELEMS;
        __nv_bfloat16* bs = as + A_ELEMS;
#pragma unroll
        for (int i = 0; i < 8; i++) {      // A: 128 rows, 16 rows per pass
            const int r = lrow + (i << 4);
            const void* sa = (const void*)(A + (size_t)(row0 + r) * lda + ko + lcol);
            uint32_t da = (uint32_t)__cvta_generic_to_shared(&as[r * AST + lcol]);
            asm volatile("cp.async.cg.shared.global [%0], [%1], 16;" :: "r"(da), "l"(sa));
        }
#pragma unroll
        for (int i = 0; i < 8; i++) {      // B: 128 rows
            const int r = lrow + (i << 4);
            const void* sb = (const void*)(B + (size_t)(col0 + r) * ldb + ko + lcol);
            uint32_t db = (uint32_t)__cvta_generic_to_shared(&bs[r * AST + lcol]);
            asm volatile("cp.async.cg.shared.global [%0], [%1], 16;" :: "r"(db), "l"(sb));
        }
        asm volatile("cp.async.commit_group;" ::: "memory");
    };

    // Prologue: fill all 3 stages, arm k0 fragments of tile 0.
    LDT(0); LDT(1); LDT(2);
    asm volatile("cp.async.wait_group 2;" ::: "memory");
    __syncthreads();

    uint32_t af[2][4][4], bf[2][4][4];
#pragma unroll
    for (int mi = 0; mi < 4; mi++)
        LDSM_X4(af[0][mi][0], af[0][mi][1], af[0][mi][2], af[0][mi][3],
                aBase[0] + mi * (16 * AST * 2));
#pragma unroll
    for (int n2 = 0; n2 < 4; n2++)
        LDSM_X4(bf[0][n2][0], bf[0][n2][1], bf[0][n2][2], bf[0][n2][3],
                bBase[0] + n2 * (16 * AST * 2));

    for (int t = 0; t < ntiles; t++) {
        const int st = t % ST;
        const uint32_t ab = aBase[st], bb = bBase[st];

        // k-steps 0..2: prefetch next k-step fragments, mma current
#pragma unroll
        for (int kk = 0; kk < 3; kk++) {
            const int cur = kk & 1, nxt = cur ^ 1;
            const uint32_t ak = ab + (kk + 1) * 32;
            const uint32_t bk = bb + (kk + 1) * 32;
#pragma unroll
            for (int mi = 0; mi < 4; mi++)
                LDSM_X4(af[nxt][mi][0], af[nxt][mi][1], af[nxt][mi][2], af[nxt][mi][3],
                        ak + mi * (16 * AST * 2));
#pragma unroll
            for (int n2 = 0; n2 < 4; n2++)
                LDSM_X4(bf[nxt][n2][0], bf[nxt][n2][1], bf[nxt][n2][2], bf[nxt][n2][3],
                        bk + n2 * (16 * AST * 2));
#pragma unroll
            for (int mi = 0; mi < 4; mi++)
#pragma unroll
                for (int ni = 0; ni < 8; ni++)
                    MMA16816(acc[mi][ni], af[cur][mi],
                             bf[cur][ni >> 1][(ni & 1) << 1],
                             bf[cur][ni >> 1][((ni & 1) << 1) + 1]);
        }

        // k-step 3: publish stage t+1, preload its k0 fragments, then mma k3.
        if (t + 1 < ntiles) {
            if (t + 3 <= ntiles) { asm volatile("cp.async.wait_group 1;" ::: "memory"); }
            else                 { asm volatile("cp.async.wait_group 0;" ::: "memory"); }
            __syncthreads();                       // publish stage t+1; drain stage t reads
            const int sn = (t + 1) % ST;
#pragma unroll
            for (int mi = 0; mi < 4; mi++)
                LDSM_X4(af[0][mi][0], af[0][mi][1], af[0][mi][2], af[0][mi][3],
                        aBase[sn] + mi * (16 * AST * 2));
#pragma unroll
            for (int n2 = 0; n2 < 4; n2++)
                LDSM_X4(bf[0][n2][0], bf[0][n2][1], bf[0][n2][2], bf[0][n2][3],
                        bBase[sn] + n2 * (16 * AST * 2));
        }
#pragma unroll
        for (int mi = 0; mi < 4; mi++)
#pragma unroll
            for (int ni = 0; ni < 8; ni++)
                MMA16816(acc[mi][ni], af[1][mi],
                         bf[1][ni >> 1][(ni & 1) << 1],
                         bf[1][ni >> 1][((ni & 1) << 1) + 1]);

        if (t + 3 < ntiles) LDT(t + 3);            // refill stage just drained
    }
    __syncthreads();
}

// ---------------------------------------------------------------------------
// Kernel: QKV projections (z = 0/1/2 -> Q/K/V), epilogue writes bf16 splits.
// ---------------------------------------------------------------------------
__global__ __launch_bounds__(128, 2) void proj_kernel(
    const float* __restrict__ bq, const float* __restrict__ bk,
    const float* __restrict__ bv)
{
    const int z = blockIdx.z;
    const __nv_bfloat16* W = (z == 0) ? g_wq : (z == 1) ? g_wk : g_wv;
    const float* bias      = (z == 0) ? bq   : (z == 1) ? bk   : bv;
    const int row0 = blockIdx.y * TM, col0 = blockIdx.x * TN;

    float acc[4][8][4];
#pragma unroll
    for (int i = 0; i < 4; i++)
#pragma unroll
        for (int j = 0; j < 8; j++)
#pragma unroll
            for (int q = 0; q < 4; q++) acc[i][j][q] = 0.f;

    gemm_core(g_xs, row0, K3, W, col0, K3, K3 / TK, KLin{}, acc);

    const int lane = threadIdx.x & 31, warp = threadIdx.x >> 5;
    const int wm = (warp & 1) << 6, wn = (warp >> 1) << 6;
    const int g = lane >> 2, tig = lane & 3;

#pragma unroll
    for (int mi = 0; mi < 4; mi++)
#pragma unroll
        for (int ni = 0; ni < 8; ni++) {
            const int n = col0 + wn + (ni << 3) + (tig << 1);
            const float b0 = bias[n], b1 = bias[n + 1];
#pragma unroll
            for (int rr = 0; rr < 2; rr++) {
                const int m = row0 + wm + (mi << 4) + g + rr * 8;
                float v0 = acc[mi][ni][rr * 2 + 0] + b0;
                float v1 = acc[mi][ni][rr * 2 + 1] + b1;
                __nv_bfloat16 h0, l0, h1, l1;
                split2(v0, h0, l0); split2(v1, h1, l1);
                if (z == 0) {          // Q: A-type [hi|lo|hi]
                    __nv_bfloat16* r = g_qs + (size_t)m * K3 + n;
                    __nv_bfloat162 th; th.x = h0; th.y = h1;
                    __nv_bfloat162 tl; tl.x = l0; tl.y = l1;
                    *(__nv_bfloat162*)(r)          = th;
                    *(__nv_bfloat162*)(r + DD)     = tl;
                    *(__nv_bfloat162*)(r + 2 * DD) = th;
                } else if (z == 1) {   // K: B-type [hi|hi|lo]
                    __nv_bfloat16* r = g_ks + (size_t)m * K3 + n;
                    __nv_bfloat162 th; th.x = h0; th.y = h1;
                    __nv_bfloat162 tl; tl.x = l0; tl.y = l1;
                    *(__nv_bfloat162*)(r)          = th;
                    *(__nv_bfloat162*)(r + DD)     = th;
                    *(__nv_bfloat162*)(r + 2 * DD) = tl;
                } else {               // V: transposed into g_vt[b][d][3S], B-type
                    const int b = m >> 11, s = m & (SS - 1);
                    __nv_bfloat16* r0 = g_vt + ((size_t)b * DD + n) * S3 + s;
                    r0[0] = h0; r0[SS] = h0; r0[2 * SS] = l0;
                    __nv_bfloat16* r1 = g_vt + ((size_t)b * DD + n + 1) * S3 + s;
                    r1[0] = h1; r1[SS] = h1; r1[2 * SS] = l1;
                }
            }
        }
}

// ---------------------------------------------------------------------------
// Kernel: scores = Q K^T / sqrt(D); causal upper blocks skipped entirely.
// ---------------------------------------------------------------------------
__global__ __launch_bounds__(128, 2) void scores_kernel()
{
    const int bx = blockIdx.x, by = blockIdx.y, b = blockIdx.z;
    if (bx > by) return;
    const __nv_bfloat16* A  = g_qs + (size_t)b * SS * K3;
    const __nv_bfloat16* Bp = g_ks + (size_t)b * SS * K3;
    const int row0 = by * TM, col0 = bx * TN;

    float acc[4][8][4];
#pragma unroll
    for (int i = 0; i < 4; i++)
#pragma unroll
        for (int j = 0; j < 8; j++)
#pragma unroll
            for (int q = 0; q < 4; q++) acc[i][j][q] = 0.f;

    gemm_core(A, row0, K3, Bp, col0, K3, K3 / TK, KLin{}, acc);

    float* C = g_sc + (size_t)b * SS * SS;
    const int lane = threadIdx.x & 31, warp = threadIdx.x >> 5;
    const int wm = (warp & 1) << 6, wn = (warp >> 1) << 6;
    const int g = lane >> 2, tig = lane & 3;

#pragma unroll
    for (int mi = 0; mi < 4; mi++)
#pragma unroll
        for (int ni = 0; ni < 8; ni++) {
            const int n = col0 + wn + (ni << 3) + (tig << 1);
#pragma unroll
            for (int rr = 0; rr < 2; rr++) {
                const int m = row0 + wm + (mi << 4) + g + rr * 8;
                float2 v;
                v.x = acc[mi][ni][rr * 2 + 0] * 0.03125f;
                v.y = acc[mi][ni][rr * 2 + 1] * 0.03125f;
                *(float2*)(C + (size_t)m * SS + n) = v;
            }
        }
}

// ---------------------------------------------------------------------------
// Kernel: causal row softmax; writes split weights (A-type) with zero fill.
// ---------------------------------------------------------------------------
__global__ __launch_bounds__(256) void softmax_kernel()
{
    const int row = blockIdx.x;
    const int b = row >> 11;
    const int i = row & (SS - 1);
    const float* p = g_sc + (size_t)b * SS * SS + (size_t)i * SS;
    __nv_bfloat16* o = g_ps + (size_t)b * SS * S3 + (size_t)i * S3;
    const int len = i + 1;
    const int tid = threadIdx.x;
    const int lane = tid & 31, wid = tid >> 5;
    __shared__ float red[8];

    float m = __int_as_float(0xff800000);
    float xv[8];
#pragma unroll
    for (int jj = 0; jj < 8; jj++) {
        int j = tid + jj * 256;
        xv[jj] = (j < len) ? p[j] : __int_as_float(0xff800000);
        m = fmaxf(m, xv[jj]);
    }
#pragma unroll
    for (int off = 16; off; off >>= 1) m = fmaxf(m, __shfl_xor_sync(0xffffffffu, m, off));
    if (lane == 0) red[wid] = m;
    __syncthreads();
    if (tid == 0) {
        float mm = red[0];
#pragma unroll
        for (int w = 1; w < 8; w++) mm = fmaxf(mm, red[w]);
        red[0] = mm;
    }
    __syncthreads();
    m = red[0];
    __syncthreads();

    float s = 0.f;
    float ev[8];
#pragma unroll
    for (int jj = 0; jj < 8; jj++) {
        int j = tid + jj * 256;
        ev[jj] = (j < len) ? __expf(xv[jj] - m) : 0.f;
        s += ev[jj];
    }
#pragma unroll
    for (int off = 16; off; off >>= 1) s += __shfl_xor_sync(0xffffffffu, s, off);
    if (lane == 0) red[wid] = s;
    __syncthreads();
    if (tid == 0) {
        float ss = 0.f;
#pragma unroll
        for (int w = 0; w < 8; w++) ss += red[w];
        red[0] = ss;
    }
    __syncthreads();
    const float inv = 1.f / red[0];

#pragma unroll
    for (int jj = 0; jj < 8; jj++) {
        int j = tid + jj * 256;
        float w = ev[jj] * inv;
        __nv_bfloat16 h, l;
        split2(w, h, l);
        o[j] = h; o[SS + j] = l; o[2 * SS + j] = h;        // A-type
    }
}

// ---------------------------------------------------------------------------
// Kernel: out = P V ; K runs 3 causal-capped segments (hi, lo, hi parts).
// ---------------------------------------------------------------------------
__global__ __launch_bounds__(128, 2) void pv_kernel(float* __restrict__ out)
{
    const int bx = blockIdx.x, by = blockIdx.y, b = blockIdx.z;
    const __nv_bfloat16* A  = g_ps + (size_t)b * SS * S3;
    const __nv_bfloat16* Bp = g_vt + (size_t)b * DD * S3;
    const int row0 = by * TM, col0 = bx * TN;
    const int tps = (row0 + TM) / TK;      // causal cap per segment

    float acc[4][8][4];
#pragma unroll
    for (int i = 0; i < 4; i++)
#pragma unroll
        for (int j = 0; j < 8; j++)
#pragma unroll
            for (int q = 0; q < 4; q++) acc[i][j][q] = 0.f;

    gemm_core(A, row0, S3, Bp, col0, S3, 3 * tps, KSeg{tps}, acc);

    float* C = out + (size_t)b * SS * DD;
    const int lane = threadIdx.x & 31, warp = threadIdx.x >> 5;
    const int wm = (warp & 1) << 6, wn = (warp >> 1) << 6;
    const int g = lane >> 2, tig = lane & 3;

#pragma unroll
    for (int mi = 0; mi < 4; mi++)
#pragma unroll
        for (int ni = 0; ni < 8; ni++) {
            const int n = col0 + wn + (ni << 3) + (tig << 1);
#pragma unroll
            for (int rr = 0; rr < 2; rr++) {
                const int m = row0 + wm + (mi << 4) + g + rr * 8;
                float2 v;
                v.x = acc[mi][ni][rr * 2 + 0];
                v.y = acc[mi][ni][rr * 2 + 1];
                *(float2*)(C + (size_t)m * DD + n) = v;
            }
        }
}

// ---------------------------------------------------------------------------
extern "C" void kernel_launch(void* const* d_in, const int* in_sizes, int n_in,
                              void* d_out, int out_size)
{
    const float* x  = (const float*)d_in[0];
    const float* Wq = (const float*)d_in[1];
    const float* bq = (const float*)d_in[2];
    const float* Wk = (const float*)d_in[3];
    const float* bk = (const float*)d_in[4];
    const float* Wv = (const float*)d_in[5];
    const float* bv = (const float*)d_in[6];
    float* out = (float*)d_out;

    cudaFuncSetAttribute(proj_kernel,   cudaFuncAttributeMaxDynamicSharedMemorySize, DYN_BYTES);
    cudaFuncSetAttribute(scores_kernel, cudaFuncAttributeMaxDynamicSharedMemorySize, DYN_BYTES);
    cudaFuncSetAttribute(pv_kernel,     cudaFuncAttributeMaxDynamicSharedMemorySize, DYN_BYTES);

    split_x_kernel<<<(MM * DD) / 256, 256>>>(x);
    split_w_kernel<<<dim3((DD * DD) / 256, 1, 3), 256>>>(Wq, Wk, Wv);
    proj_kernel<<<dim3(DD / TN, MM / TM, 3), 128, DYN_BYTES>>>(bq, bk, bv);
    scores_kernel<<<dim3(SS / TN, SS / TM, BB), 128, DYN_BYTES>>>();
    softmax_kernel<<<BB * SS, 256>>>();
    pv_kernel<<<dim3(DD / TN, SS / TM, BB), 128, DYN_BYTES>>>(out);
}

// round 11
// speedup vs baseline: 2.5150x; 1.5235x over previous
#include <cuda_runtime.h>
#include <cuda_fp16.h>
#include <cstdint>

// Problem constants
#define BB 4
#define SS 2048
#define DD 1024
#define MM (BB*SS)       // 8192
#define K2 (2*DD)        // 2048  (2-term split K for projections/scores)
#define S2 (2*SS)        // 4096  (2-term split K for PV)

// GEMM tiling (R8 shell: 8 warps, warp tile 64x32)
#define TM 128
#define TN 128
#define TK 64
#define AST 72           // TK + 8 pad: 144B row stride, ldmatrix conflict-free
#define ST 3             // cp.async stages (110.6KB smem -> 2 CTA/SM)

#define A_ELEMS (TM*AST)
#define STAGE_ELEMS (2*A_ELEMS)
#define DYN_BYTES (ST*STAGE_ELEMS*2)  // 110592 B dynamic smem

// ---------------------------------------------------------------------------
// Scratch (__device__ globals).  2-term fp16 split:
//   A-type row = [hi | lo]  (operand split),  B-type row = [hi | hi]
//   => GEMM over 2K computes (ah+al)*bh; dropped term a*(b-bh) ~ 2^-12.6.
// ---------------------------------------------------------------------------
__device__ __half g_xs[(size_t)MM * K2];
__device__ __half g_wq[(size_t)DD * K2];
__device__ __half g_wk[(size_t)DD * K2];
__device__ __half g_wv[(size_t)DD * K2];
__device__ __half g_qs[(size_t)MM * K2];
__device__ __half g_ks[(size_t)MM * K2];
__device__ __half g_vt[(size_t)BB * DD * S2];
__device__ float  g_sc[(size_t)BB * SS * SS];
__device__ __half g_ps[(size_t)BB * SS * S2];

__device__ __forceinline__ void split2(float v, __half& h, __half& l) {
    h = __float2half(v);
    l = __float2half(v - __half2float(h));
}

// ---------------------------------------------------------------------------
// Split input kernels
// ---------------------------------------------------------------------------
__global__ __launch_bounds__(256) void split_x_kernel(const float* __restrict__ x)
{
    size_t idx = (size_t)blockIdx.x * 256 + threadIdx.x;
    size_t m = idx >> 10, d = idx & (DD - 1);
    __half h, l;
    split2(x[idx], h, l);
    __half* r = g_xs + m * K2;
    r[d] = h; r[DD + d] = l;                               // A-type [hi|lo]
}

__global__ __launch_bounds__(256) void split_w_kernel(
    const float* __restrict__ Wq, const float* __restrict__ Wk,
    const float* __restrict__ Wv)
{
    int z = blockIdx.z;
    size_t idx = (size_t)blockIdx.x * 256 + threadIdx.x;
    const float* W = (z == 0) ? Wq : (z == 1) ? Wk : Wv;
    __half* O = (z == 0) ? g_wq : (z == 1) ? g_wk : g_wv;
    size_t e = idx >> 10, d = idx & (DD - 1);
    __half h = __float2half(W[idx]);
    __half* r = O + e * K2;
    r[d] = h; r[DD + d] = h;                               // B-type [hi|hi]
}

// ---------------------------------------------------------------------------
// GEMM core (R8): C[128x128] = A * B^T, fp16 K-major, TK=64 tiles, 3-stage
// cp.async ring, register fragment pipeline carried across tile boundaries.
// Requires ntiles >= 3 (min call site: pv by=0 -> 4).
// ---------------------------------------------------------------------------
struct KLin {
    __device__ __forceinline__ int operator()(int t) const { return t * TK; }
};
struct KSeg {
    int tps;  // tiles per segment
    __device__ __forceinline__ int operator()(int t) const {
        int s = t / tps; return s * SS + (t - s * tps) * TK;
    }
};

#define LDSM_X4(r0, r1, r2, r3, addr) \
    asm volatile("ldmatrix.sync.aligned.m8n8.x4.shared.b16 {%0,%1,%2,%3}, [%4];" \
                 : "=r"(r0), "=r"(r1), "=r"(r2), "=r"(r3) : "r"(addr))

#define MMA16816(c, a, b0, b1)                                                \
    asm volatile(                                                             \
        "mma.sync.aligned.m16n8k16.row.col.f32.f16.f16.f32 "                  \
        "{%0,%1,%2,%3}, {%4,%5,%6,%7}, {%8,%9}, {%0,%1,%2,%3};\n"             \
        : "+f"((c)[0]), "+f"((c)[1]), "+f"((c)[2]), "+f"((c)[3])              \
        : "r"((a)[0]), "r"((a)[1]), "r"((a)[2]), "r"((a)[3]), "r"(b0), "r"(b1))

template <typename KF>
__device__ __forceinline__ void gemm_core(
    const __half* __restrict__ A, int row0, size_t lda,
    const __half* __restrict__ B, int col0, size_t ldb,
    int ntiles, KF koff, float acc[4][4][4])
{
    extern __shared__ __align__(16) __half smem[];

    const int tid  = threadIdx.x;
    const int lane = tid & 31, warp = tid >> 5;
    const int wm = (warp & 1) << 6;       // 0/64
    const int wn = (warp >> 1) << 5;      // 0/32/64/96
    const int lr  = lane & 7;
    const int seg = lane >> 3;            // 0..3
    const int lrow = tid >> 3;            // loader row base 0..31
    const int lcol = (tid & 7) << 3;      // loader elem col 0..56

    uint32_t aBase[ST], bBase[ST];
#pragma unroll
    for (int s = 0; s < ST; s++) {
        aBase[s] = (uint32_t)__cvta_generic_to_shared(
            smem + s * STAGE_ELEMS + (wm + ((seg & 1) << 3) + lr) * AST + ((seg >> 1) << 3));
        bBase[s] = (uint32_t)__cvta_generic_to_shared(
            smem + s * STAGE_ELEMS + A_ELEMS + (wn + ((seg >> 1) << 3) + lr) * AST + ((seg & 1) << 3));
    }

    auto LDT = [&](int t) {
        const int ko = koff(t);
        __half* as = smem + (t % ST) * STAGE_ELEMS;
        __half* bs = as + A_ELEMS;
#pragma unroll
        for (int i = 0; i < 4; i++) {
            const int r = lrow + (i << 5);
            const void* sa = (const void*)(A + (size_t)(row0 + r) * lda + ko + lcol);
            uint32_t da = (uint32_t)__cvta_generic_to_shared(&as[r * AST + lcol]);
            asm volatile("cp.async.cg.shared.global [%0], [%1], 16;" :: "r"(da), "l"(sa));
            const void* sb = (const void*)(B + (size_t)(col0 + r) * ldb + ko + lcol);
            uint32_t db = (uint32_t)__cvta_generic_to_shared(&bs[r * AST + lcol]);
            asm volatile("cp.async.cg.shared.global [%0], [%1], 16;" :: "r"(db), "l"(sb));
        }
        asm volatile("cp.async.commit_group;" ::: "memory");
    };

    // Prologue: fill all 3 stages, arm k0 fragments of tile 0.
    LDT(0); LDT(1); LDT(2);
    asm volatile("cp.async.wait_group 2;" ::: "memory");
    __syncthreads();

    uint32_t af[2][4][4], bf[2][2][4];
#pragma unroll
    for (int mi = 0; mi < 4; mi++)
        LDSM_X4(af[0][mi][0], af[0][mi][1], af[0][mi][2], af[0][mi][3],
                aBase[0] + mi * (16 * AST * 2));
#pragma unroll
    for (int n2 = 0; n2 < 2; n2++)
        LDSM_X4(bf[0][n2][0], bf[0][n2][1], bf[0][n2][2], bf[0][n2][3],
                bBase[0] + n2 * (16 * AST * 2));

    for (int t = 0; t < ntiles; t++) {
        const int st = t % ST;
        const uint32_t ab = aBase[st], bb = bBase[st];

        // k-steps 0..2: prefetch next k-step fragments, mma current
#pragma unroll
        for (int kk = 0; kk < 3; kk++) {
            const int cur = kk & 1, nxt = cur ^ 1;
            const uint32_t ak = ab + (kk + 1) * 32;
            const uint32_t bk = bb + (kk + 1) * 32;
#pragma unroll
            for (int mi = 0; mi < 4; mi++)
                LDSM_X4(af[nxt][mi][0], af[nxt][mi][1], af[nxt][mi][2], af[nxt][mi][3],
                        ak + mi * (16 * AST * 2));
#pragma unroll
            for (int n2 = 0; n2 < 2; n2++)
                LDSM_X4(bf[nxt][n2][0], bf[nxt][n2][1], bf[nxt][n2][2], bf[nxt][n2][3],
                        bk + n2 * (16 * AST * 2));
#pragma unroll
            for (int mi = 0; mi < 4; mi++)
#pragma unroll
                for (int ni = 0; ni < 4; ni++)
                    MMA16816(acc[mi][ni], af[cur][mi],
                             bf[cur][ni >> 1][(ni & 1) << 1],
                             bf[cur][ni >> 1][((ni & 1) << 1) + 1]);
        }

        // k-step 3: publish stage t+1, preload its k0 fragments, then mma k3.
        if (t + 1 < ntiles) {
            if (t + 3 <= ntiles) { asm volatile("cp.async.wait_group 1;" ::: "memory"); }
            else                 { asm volatile("cp.async.wait_group 0;" ::: "memory"); }
            __syncthreads();
            const int sn = (t + 1) % ST;
#pragma unroll
            for (int mi = 0; mi < 4; mi++)
                LDSM_X4(af[0][mi][0], af[0][mi][1], af[0][mi][2], af[0][mi][3],
                        aBase[sn] + mi * (16 * AST * 2));
#pragma unroll
            for (int n2 = 0; n2 < 2; n2++)
                LDSM_X4(bf[0][n2][0], bf[0][n2][1], bf[0][n2][2], bf[0][n2][3],
                        bBase[sn] + n2 * (16 * AST * 2));
        }
#pragma unroll
        for (int mi = 0; mi < 4; mi++)
#pragma unroll
            for (int ni = 0; ni < 4; ni++)
                MMA16816(acc[mi][ni], af[1][mi],
                         bf[1][ni >> 1][(ni & 1) << 1],
                         bf[1][ni >> 1][((ni & 1) << 1) + 1]);

        if (t + 3 < ntiles) LDT(t + 3);
    }
    __syncthreads();
}

// ---------------------------------------------------------------------------
// Kernel: QKV projections (z = 0/1/2 -> Q/K/V), epilogue writes fp16 splits.
// ---------------------------------------------------------------------------
__global__ __launch_bounds__(256, 2) void proj_kernel(
    const float* __restrict__ bq, const float* __restrict__ bk,
    const float* __restrict__ bv)
{
    const int z = blockIdx.z;
    const __half* W   = (z == 0) ? g_wq : (z == 1) ? g_wk : g_wv;
    const float* bias = (z == 0) ? bq   : (z == 1) ? bk   : bv;
    const int row0 = blockIdx.y * TM, col0 = blockIdx.x * TN;

    float acc[4][4][4];
#pragma unroll
    for (int i = 0; i < 4; i++)
#pragma unroll
        for (int j = 0; j < 4; j++)
#pragma unroll
            for (int q = 0; q < 4; q++) acc[i][j][q] = 0.f;

    gemm_core(g_xs, row0, K2, W, col0, K2, K2 / TK, KLin{}, acc);

    const int lane = threadIdx.x & 31, warp = threadIdx.x >> 5;
    const int wm = (warp & 1) << 6, wn = (warp >> 1) << 5;
    const int g = lane >> 2, tig = lane & 3;

#pragma unroll
    for (int mi = 0; mi < 4; mi++)
#pragma unroll
        for (int ni = 0; ni < 4; ni++) {
            const int n = col0 + wn + (ni << 3) + (tig << 1);
            const float b0 = bias[n], b1 = bias[n + 1];
#pragma unroll
            for (int rr = 0; rr < 2; rr++) {
                const int m = row0 + wm + (mi << 4) + g + rr * 8;
                float v0 = acc[mi][ni][rr * 2 + 0] + b0;
                float v1 = acc[mi][ni][rr * 2 + 1] + b1;
                __half h0, l0, h1, l1;
                split2(v0, h0, l0); split2(v1, h1, l1);
                if (z == 0) {          // Q: A-type [hi|lo]
                    __half* r = g_qs + (size_t)m * K2 + n;
                    __half2 th; th.x = h0; th.y = h1;
                    __half2 tl; tl.x = l0; tl.y = l1;
                    *(__half2*)(r)      = th;
                    *(__half2*)(r + DD) = tl;
                } else if (z == 1) {   // K: B-type [hi|hi]
                    __half* r = g_ks + (size_t)m * K2 + n;
                    __half2 th; th.x = h0; th.y = h1;
                    *(__half2*)(r)      = th;
                    *(__half2*)(r + DD) = th;
                } else {               // V: transposed into g_vt[b][d][2S], B-type
                    const int b = m >> 11, s = m & (SS - 1);
                    __half* r0 = g_vt + ((size_t)b * DD + n) * S2 + s;
                    r0[0] = h0; r0[SS] = h0;
                    __half* r1 = g_vt + ((size_t)b * DD + n + 1) * S2 + s;
                    r1[0] = h1; r1[SS] = h1;
                }
            }
        }
}

// ---------------------------------------------------------------------------
// Kernel: scores = Q K^T / sqrt(D); causal upper blocks skipped entirely.
// ---------------------------------------------------------------------------
__global__ __launch_bounds__(256, 2) void scores_kernel()
{
    const int bx = blockIdx.x, by = blockIdx.y, b = blockIdx.z;
    if (bx > by) return;
    const __half* A  = g_qs + (size_t)b * SS * K2;
    const __half* Bp = g_ks + (size_t)b * SS * K2;
    const int row0 = by * TM, col0 = bx * TN;

    float acc[4][4][4];
#pragma unroll
    for (int i = 0; i < 4; i++)
#pragma unroll
        for (int j = 0; j < 4; j++)
#pragma unroll
            for (int q = 0; q < 4; q++) acc[i][j][q] = 0.f;

    gemm_core(A, row0, K2, Bp, col0, K2, K2 / TK, KLin{}, acc);

    float* C = g_sc + (size_t)b * SS * SS;
    const int lane = threadIdx.x & 31, warp = threadIdx.x >> 5;
    const int wm = (warp & 1) << 6, wn = (warp >> 1) << 5;
    const int g = lane >> 2, tig = lane & 3;

#pragma unroll
    for (int mi = 0; mi < 4; mi++)
#pragma unroll
        for (int ni = 0; ni < 4; ni++) {
            const int n = col0 + wn + (ni << 3) + (tig << 1);
#pragma unroll
            for (int rr = 0; rr < 2; rr++) {
                const int m = row0 + wm + (mi << 4) + g + rr * 8;
                float2 v;
                v.x = acc[mi][ni][rr * 2 + 0] * 0.03125f;
                v.y = acc[mi][ni][rr * 2 + 1] * 0.03125f;
                *(float2*)(C + (size_t)m * SS + n) = v;
            }
        }
}

// ---------------------------------------------------------------------------
// Kernel: causal row softmax; writes 2-term fp16 weights (A-type), zero fill.
// ---------------------------------------------------------------------------
__global__ __launch_bounds__(256) void softmax_kernel()
{
    const int row = blockIdx.x;
    const int b = row >> 11;
    const int i = row & (SS - 1);
    const float* p = g_sc + (size_t)b * SS * SS + (size_t)i * SS;
    __half* o = g_ps + (size_t)b * SS * S2 + (size_t)i * S2;
    const int len = i + 1;
    const int tid = threadIdx.x;
    const int lane = tid & 31, wid = tid >> 5;
    __shared__ float red[8];

    float m = __int_as_float(0xff800000);
    float xv[8];
#pragma unroll
    for (int jj = 0; jj < 8; jj++) {
        int j = tid + jj * 256;
        xv[jj] = (j < len) ? p[j] : __int_as_float(0xff800000);
        m = fmaxf(m, xv[jj]);
    }
#pragma unroll
    for (int off = 16; off; off >>= 1) m = fmaxf(m, __shfl_xor_sync(0xffffffffu, m, off));
    if (lane == 0) red[wid] = m;
    __syncthreads();
    if (tid == 0) {
        float mm = red[0];
#pragma unroll
        for (int w = 1; w < 8; w++) mm = fmaxf(mm, red[w]);
        red[0] = mm;
    }
    __syncthreads();
    m = red[0];
    __syncthreads();

    float s = 0.f;
    float ev[8];
#pragma unroll
    for (int jj = 0; jj < 8; jj++) {
        int j = tid + jj * 256;
        ev[jj] = (j < len) ? __expf(xv[jj] - m) : 0.f;
        s += ev[jj];
    }
#pragma unroll
    for (int off = 16; off; off >>= 1) s += __shfl_xor_sync(0xffffffffu, s, off);
    if (lane == 0) red[wid] = s;
    __syncthreads();
    if (tid == 0) {
        float ss = 0.f;
#pragma unroll
        for (int w = 0; w < 8; w++) ss += red[w];
        red[0] = ss;
    }
    __syncthreads();
    const float inv = 1.f / red[0];

#pragma unroll
    for (int jj = 0; jj < 8; jj++) {
        int j = tid + jj * 256;
        float w = ev[jj] * inv;
        __half h, l;
        split2(w, h, l);
        o[j] = h; o[SS + j] = l;               // A-type [hi|lo]
    }
}

// ---------------------------------------------------------------------------
// Kernel: out = P V ; K runs 2 causal-capped segments (hi, lo parts).
// ---------------------------------------------------------------------------
__global__ __launch_bounds__(256, 2) void pv_kernel(float* __restrict__ out)
{
    const int bx = blockIdx.x, by = blockIdx.y, b = blockIdx.z;
    const __half* A  = g_ps + (size_t)b * SS * S2;
    const __half* Bp = g_vt + (size_t)b * DD * S2;
    const int row0 = by * TM, col0 = bx * TN;
    const int tps = (row0 + TM) / TK;      // causal cap per segment

    float acc[4][4][4];
#pragma unroll
    for (int i = 0; i < 4; i++)
#pragma unroll
        for (int j = 0; j < 4; j++)
#pragma unroll
            for (int q = 0; q < 4; q++) acc[i][j][q] = 0.f;

    gemm_core(A, row0, S2, Bp, col0, S2, 2 * tps, KSeg{tps}, acc);

    float* C = out + (size_t)b * SS * DD;
    const int lane = threadIdx.x & 31, warp = threadIdx.x >> 5;
    const int wm = (warp & 1) << 6, wn = (warp >> 1) << 5;
    const int g = lane >> 2, tig = lane & 3;

#pragma unroll
    for (int mi = 0; mi < 4; mi++)
#pragma unroll
        for (int ni = 0; ni < 4; ni++) {
            const int n = col0 + wn + (ni << 3) + (tig << 1);
#pragma unroll
            for (int rr = 0; rr < 2; rr++) {
                const int m = row0 + wm + (mi << 4) + g + rr * 8;
                float2 v;
                v.x = acc[mi][ni][rr * 2 + 0];
                v.y = acc[mi][ni][rr * 2 + 1];
                *(float2*)(C + (size_t)m * DD + n) = v;
            }
        }
}

// ---------------------------------------------------------------------------
extern "C" void kernel_launch(void* const* d_in, const int* in_sizes, int n_in,
                              void* d_out, int out_size)
{
    const float* x  = (const float*)d_in[0];
    const float* Wq = (const float*)d_in[1];
    const float* bq = (const float*)d_in[2];
    const float* Wk = (const float*)d_in[3];
    const float* bk = (const float*)d_in[4];
    const float* Wv = (const float*)d_in[5];
    const float* bv = (const float*)d_in[6];
    float* out = (float*)d_out;

    cudaFuncSetAttribute(proj_kernel,   cudaFuncAttributeMaxDynamicSharedMemorySize, DYN_BYTES);
    cudaFuncSetAttribute(scores_kernel, cudaFuncAttributeMaxDynamicSharedMemorySize, DYN_BYTES);
    cudaFuncSetAttribute(pv_kernel,     cudaFuncAttributeMaxDynamicSharedMemorySize, DYN_BYTES);

    split_x_kernel<<<(MM * DD) / 256, 256>>>(x);
    split_w_kernel<<<dim3((DD * DD) / 256, 1, 3), 256>>>(Wq, Wk, Wv);
    proj_kernel<<<dim3(DD / TN, MM / TM, 3), 256, DYN_BYTES>>>(bq, bk, bv);
    scores_kernel<<<dim3(SS / TN, SS / TM, BB), 256, DYN_BYTES>>>();
    softmax_kernel<<<BB * SS, 256>>>();
    pv_kernel<<<dim3(DD / TN, SS / TM, BB), 256, DYN_BYTES>>>(out);
}

// round 12
// speedup vs baseline: 3.2151x; 1.2784x over previous
#include <cuda_runtime.h>
#include <cuda_fp16.h>
#include <cstdint>

// Problem constants
#define BB 4
#define SS 2048
#define DD 1024
#define MM (BB*SS)       // 8192
#define K2 (2*DD)        // 2048  (2-term split K, projections only)

// GEMM tiling (8 warps, warp tile 64x32)
#define TM 128
#define TN 128
#define TK 64
#define AST 72           // TK + 8 pad: 144B row stride, ldmatrix conflict-free
#define ST 3             // cp.async stages (110.6KB smem -> 2 CTA/SM)

#define A_ELEMS (TM*AST)
#define STAGE_ELEMS (2*A_ELEMS)
#define DYN_BYTES (ST*STAGE_ELEMS*2)  // 110592 B dynamic smem

// ---------------------------------------------------------------------------
// Scratch.  Proj uses 2-term split: x = [xh|xl] (A-type), W = [Wh|Wh]
// (B-type) so one K=2048 GEMM computes (xh+xl)*Wh.  Downstream GEMMs
// (scores, PV) run plain fp16 over K=1024 / causal-capped seq.
// ---------------------------------------------------------------------------
__device__ __half g_xs[(size_t)MM * K2];
__device__ __half g_wq[(size_t)DD * K2];
__device__ __half g_wk[(size_t)DD * K2];
__device__ __half g_wv[(size_t)DD * K2];
__device__ __half g_qs[(size_t)MM * DD];        // Q fp16
__device__ __half g_ks[(size_t)MM * DD];        // K fp16
__device__ __half g_vt[(size_t)BB * DD * SS];   // V^T fp16
__device__ float  g_sc[(size_t)BB * SS * SS];   // scores fp32
__device__ __half g_ps[(size_t)BB * SS * SS];   // softmax weights fp16

__device__ __forceinline__ void split2(float v, __half& h, __half& l) {
    h = __float2half(v);
    l = __float2half(v - __half2float(h));
}

// ---------------------------------------------------------------------------
// Split input kernels
// ---------------------------------------------------------------------------
__global__ __launch_bounds__(256) void split_x_kernel(const float* __restrict__ x)
{
    size_t idx = (size_t)blockIdx.x * 256 + threadIdx.x;
    size_t m = idx >> 10, d = idx & (DD - 1);
    __half h, l;
    split2(x[idx], h, l);
    __half* r = g_xs + m * K2;
    r[d] = h; r[DD + d] = l;                               // A-type [hi|lo]
}

__global__ __launch_bounds__(256) void split_w_kernel(
    const float* __restrict__ Wq, const float* __restrict__ Wk,
    const float* __restrict__ Wv)
{
    int z = blockIdx.z;
    size_t idx = (size_t)blockIdx.x * 256 + threadIdx.x;
    const float* W = (z == 0) ? Wq : (z == 1) ? Wk : Wv;
    __half* O = (z == 0) ? g_wq : (z == 1) ? g_wk : g_wv;
    size_t e = idx >> 10, d = idx & (DD - 1);
    __half h = __float2half(W[idx]);
    __half* r = O + e * K2;
    r[d] = h; r[DD + d] = h;                               // B-type [hi|hi]
}

// ---------------------------------------------------------------------------
// GEMM core: C[128x128] = A * B^T, fp16 K-major, TK=64 tiles, 3-stage
// cp.async ring, register fragment pipeline carried across tile boundaries.
// Works for ntiles >= 2 (prologue prefetch of tile 2 is never consumed when
// ntiles == 2; callers guarantee those addresses are in-bounds).
// ---------------------------------------------------------------------------
#define LDSM_X4(r0, r1, r2, r3, addr) \
    asm volatile("ldmatrix.sync.aligned.m8n8.x4.shared.b16 {%0,%1,%2,%3}, [%4];" \
                 : "=r"(r0), "=r"(r1), "=r"(r2), "=r"(r3) : "r"(addr))

#define MMA16816(c, a, b0, b1)                                                \
    asm volatile(                                                             \
        "mma.sync.aligned.m16n8k16.row.col.f32.f16.f16.f32 "                  \
        "{%0,%1,%2,%3}, {%4,%5,%6,%7}, {%8,%9}, {%0,%1,%2,%3};\n"             \
        : "+f"((c)[0]), "+f"((c)[1]), "+f"((c)[2]), "+f"((c)[3])              \
        : "r"((a)[0]), "r"((a)[1]), "r"((a)[2]), "r"((a)[3]), "r"(b0), "r"(b1))

__device__ __forceinline__ void gemm_core(
    const __half* __restrict__ A, int row0, size_t lda,
    const __half* __restrict__ B, int col0, size_t ldb,
    int ntiles, float acc[4][4][4])
{
    extern __shared__ __align__(16) __half smem[];

    const int tid  = threadIdx.x;
    const int lane = tid & 31, warp = tid >> 5;
    const int wm = (warp & 1) << 6;       // 0/64
    const int wn = (warp >> 1) << 5;      // 0/32/64/96
    const int lr  = lane & 7;
    const int seg = lane >> 3;            // 0..3
    const int lrow = tid >> 3;            // loader row base 0..31
    const int lcol = (tid & 7) << 3;      // loader elem col 0..56

    uint32_t aBase[ST], bBase[ST];
#pragma unroll
    for (int s = 0; s < ST; s++) {
        aBase[s] = (uint32_t)__cvta_generic_to_shared(
            smem + s * STAGE_ELEMS + (wm + ((seg & 1) << 3) + lr) * AST + ((seg >> 1) << 3));
        bBase[s] = (uint32_t)__cvta_generic_to_shared(
            smem + s * STAGE_ELEMS + A_ELEMS + (wn + ((seg >> 1) << 3) + lr) * AST + ((seg & 1) << 3));
    }

    auto LDT = [&](int t) {
        const int ko = t * TK;
        __half* as = smem + (t % ST) * STAGE_ELEMS;
        __half* bs = as + A_ELEMS;
#pragma unroll
        for (int i = 0; i < 4; i++) {
            const int r = lrow + (i << 5);
            const void* sa = (const void*)(A + (size_t)(row0 + r) * lda + ko + lcol);
            uint32_t da = (uint32_t)__cvta_generic_to_shared(&as[r * AST + lcol]);
            asm volatile("cp.async.cg.shared.global [%0], [%1], 16;" :: "r"(da), "l"(sa));
            const void* sb = (const void*)(B + (size_t)(col0 + r) * ldb + ko + lcol);
            uint32_t db = (uint32_t)__cvta_generic_to_shared(&bs[r * AST + lcol]);
            asm volatile("cp.async.cg.shared.global [%0], [%1], 16;" :: "r"(db), "l"(sb));
        }
        asm volatile("cp.async.commit_group;" ::: "memory");
    };

    // Prologue: fill all 3 stages, arm k0 fragments of tile 0.
    LDT(0); LDT(1); LDT(2);
    asm volatile("cp.async.wait_group 2;" ::: "memory");
    __syncthreads();

    uint32_t af[2][4][4], bf[2][2][4];
#pragma unroll
    for (int mi = 0; mi < 4; mi++)
        LDSM_X4(af[0][mi][0], af[0][mi][1], af[0][mi][2], af[0][mi][3],
                aBase[0] + mi * (16 * AST * 2));
#pragma unroll
    for (int n2 = 0; n2 < 2; n2++)
        LDSM_X4(bf[0][n2][0], bf[0][n2][1], bf[0][n2][2], bf[0][n2][3],
                bBase[0] + n2 * (16 * AST * 2));

    for (int t = 0; t < ntiles; t++) {
        const int st = t % ST;
        const uint32_t ab = aBase[st], bb = bBase[st];

        // k-steps 0..2: prefetch next k-step fragments, mma current
#pragma unroll
        for (int kk = 0; kk < 3; kk++) {
            const int cur = kk & 1, nxt = cur ^ 1;
            const uint32_t ak = ab + (kk + 1) * 32;
            const uint32_t bk = bb + (kk + 1) * 32;
#pragma unroll
            for (int mi = 0; mi < 4; mi++)
                LDSM_X4(af[nxt][mi][0], af[nxt][mi][1], af[nxt][mi][2], af[nxt][mi][3],
                        ak + mi * (16 * AST * 2));
#pragma unroll
            for (int n2 = 0; n2 < 2; n2++)
                LDSM_X4(bf[nxt][n2][0], bf[nxt][n2][1], bf[nxt][n2][2], bf[nxt][n2][3],
                        bk + n2 * (16 * AST * 2));
#pragma unroll
            for (int mi = 0; mi < 4; mi++)
#pragma unroll
                for (int ni = 0; ni < 4; ni++)
                    MMA16816(acc[mi][ni], af[cur][mi],
                             bf[cur][ni >> 1][(ni & 1) << 1],
                             bf[cur][ni >> 1][((ni & 1) << 1) + 1]);
        }

        // k-step 3: publish stage t+1, preload its k0 fragments, then mma k3.
        if (t + 1 < ntiles) {
            if (t + 3 <= ntiles) { asm volatile("cp.async.wait_group 1;" ::: "memory"); }
            else                 { asm volatile("cp.async.wait_group 0;" ::: "memory"); }
            __syncthreads();
            const int sn = (t + 1) % ST;
#pragma unroll
            for (int mi = 0; mi < 4; mi++)
                LDSM_X4(af[0][mi][0], af[0][mi][1], af[0][mi][2], af[0][mi][3],
                        aBase[sn] + mi * (16 * AST * 2));
#pragma unroll
            for (int n2 = 0; n2 < 2; n2++)
                LDSM_X4(bf[0][n2][0], bf[0][n2][1], bf[0][n2][2], bf[0][n2][3],
                        bBase[sn] + n2 * (16 * AST * 2));
        }
#pragma unroll
        for (int mi = 0; mi < 4; mi++)
#pragma unroll
            for (int ni = 0; ni < 4; ni++)
                MMA16816(acc[mi][ni], af[1][mi],
                         bf[1][ni >> 1][(ni & 1) << 1],
                         bf[1][ni >> 1][((ni & 1) << 1) + 1]);

        if (t + 3 < ntiles) LDT(t + 3);
    }
    __syncthreads();
}

// ---------------------------------------------------------------------------
// Kernel: QKV projections (z = 0/1/2 -> Q/K/V), epilogue writes plain fp16.
// ---------------------------------------------------------------------------
__global__ __launch_bounds__(256, 2) void proj_kernel(
    const float* __restrict__ bq, const float* __restrict__ bk,
    const float* __restrict__ bv)
{
    const int z = blockIdx.z;
    const __half* W   = (z == 0) ? g_wq : (z == 1) ? g_wk : g_wv;
    const float* bias = (z == 0) ? bq   : (z == 1) ? bk   : bv;
    const int row0 = blockIdx.y * TM, col0 = blockIdx.x * TN;

    float acc[4][4][4];
#pragma unroll
    for (int i = 0; i < 4; i++)
#pragma unroll
        for (int j = 0; j < 4; j++)
#pragma unroll
            for (int q = 0; q < 4; q++) acc[i][j][q] = 0.f;

    gemm_core(g_xs, row0, K2, W, col0, K2, K2 / TK, acc);

    const int lane = threadIdx.x & 31, warp = threadIdx.x >> 5;
    const int wm = (warp & 1) << 6, wn = (warp >> 1) << 5;
    const int g = lane >> 2, tig = lane & 3;

#pragma unroll
    for (int mi = 0; mi < 4; mi++)
#pragma unroll
        for (int ni = 0; ni < 4; ni++) {
            const int n = col0 + wn + (ni << 3) + (tig << 1);
            const float b0 = bias[n], b1 = bias[n + 1];
#pragma unroll
            for (int rr = 0; rr < 2; rr++) {
                const int m = row0 + wm + (mi << 4) + g + rr * 8;
                float v0 = acc[mi][ni][rr * 2 + 0] + b0;
                float v1 = acc[mi][ni][rr * 2 + 1] + b1;
                __half h0 = __float2half(v0), h1 = __float2half(v1);
                if (z < 2) {           // Q / K: plain fp16 row-major
                    __half* r = ((z == 0) ? g_qs : g_ks) + (size_t)m * DD + n;
                    __half2 th; th.x = h0; th.y = h1;
                    *(__half2*)r = th;
                } else {               // V: transposed into g_vt[b][d][S]
                    const int b = m >> 11, s = m & (SS - 1);
                    g_vt[((size_t)b * DD + n) * SS + s]     = h0;
                    g_vt[((size_t)b * DD + n + 1) * SS + s] = h1;
                }
            }
        }
}

// ---------------------------------------------------------------------------
// Kernel: scores = Q K^T / sqrt(D), fp16 K=1024; upper blocks skipped.
// ---------------------------------------------------------------------------
__global__ __launch_bounds__(256, 2) void scores_kernel()
{
    const int bx = blockIdx.x, by = blockIdx.y, b = blockIdx.z;
    if (bx > by) return;
    const __half* A  = g_qs + (size_t)b * SS * DD;
    const __half* Bp = g_ks + (size_t)b * SS * DD;
    const int row0 = by * TM, col0 = bx * TN;

    float acc[4][4][4];
#pragma unroll
    for (int i = 0; i < 4; i++)
#pragma unroll
        for (int j = 0; j < 4; j++)
#pragma unroll
            for (int q = 0; q < 4; q++) acc[i][j][q] = 0.f;

    gemm_core(A, row0, DD, Bp, col0, DD, DD / TK, acc);

    float* C = g_sc + (size_t)b * SS * SS;
    const int lane = threadIdx.x & 31, warp = threadIdx.x >> 5;
    const int wm = (warp & 1) << 6, wn = (warp >> 1) << 5;
    const int g = lane >> 2, tig = lane & 3;

#pragma unroll
    for (int mi = 0; mi < 4; mi++)
#pragma unroll
        for (int ni = 0; ni < 4; ni++) {
            const int n = col0 + wn + (ni << 3) + (tig << 1);
#pragma unroll
            for (int rr = 0; rr < 2; rr++) {
                const int m = row0 + wm + (mi << 4) + g + rr * 8;
                float2 v;
                v.x = acc[mi][ni][rr * 2 + 0] * 0.03125f;
                v.y = acc[mi][ni][rr * 2 + 1] * 0.03125f;
                *(float2*)(C + (size_t)m * SS + n) = v;
            }
        }
}

// ---------------------------------------------------------------------------
// Kernel: causal row softmax; writes plain fp16 weights, zero fill.
// ---------------------------------------------------------------------------
__global__ __launch_bounds__(256) void softmax_kernel()
{
    const int row = blockIdx.x;
    const int b = row >> 11;
    const int i = row & (SS - 1);
    const float* p = g_sc + (size_t)b * SS * SS + (size_t)i * SS;
    __half* o = g_ps + (size_t)b * SS * SS + (size_t)i * SS;
    const int len = i + 1;
    const int tid = threadIdx.x;
    const int lane = tid & 31, wid = tid >> 5;
    __shared__ float red[8];

    float m = __int_as_float(0xff800000);
    float xv[8];
#pragma unroll
    for (int jj = 0; jj < 8; jj++) {
        int j = tid + jj * 256;
        xv[jj] = (j < len) ? p[j] : __int_as_float(0xff800000);
        m = fmaxf(m, xv[jj]);
    }
#pragma unroll
    for (int off = 16; off; off >>= 1) m = fmaxf(m, __shfl_xor_sync(0xffffffffu, m, off));
    if (lane == 0) red[wid] = m;
    __syncthreads();
    if (tid == 0) {
        float mm = red[0];
#pragma unroll
        for (int w = 1; w < 8; w++) mm = fmaxf(mm, red[w]);
        red[0] = mm;
    }
    __syncthreads();
    m = red[0];
    __syncthreads();

    float s = 0.f;
    float ev[8];
#pragma unroll
    for (int jj = 0; jj < 8; jj++) {
        int j = tid + jj * 256;
        ev[jj] = (j < len) ? __expf(xv[jj] - m) : 0.f;
        s += ev[jj];
    }
#pragma unroll
    for (int off = 16; off; off >>= 1) s += __shfl_xor_sync(0xffffffffu, s, off);
    if (lane == 0) red[wid] = s;
    __syncthreads();
    if (tid == 0) {
        float ss = 0.f;
#pragma unroll
        for (int w = 0; w < 8; w++) ss += red[w];
        red[0] = ss;
    }
    __syncthreads();
    const float inv = 1.f / red[0];

#pragma unroll
    for (int jj = 0; jj < 8; jj++) {
        int j = tid + jj * 256;
        o[j] = __float2half(ev[jj] * inv);     // 0 for j > i
    }
}

// ---------------------------------------------------------------------------
// Kernel: out = P V, fp16, K capped at the diagonal of this block-row.
// ---------------------------------------------------------------------------
__global__ __launch_bounds__(256, 2) void pv_kernel(float* __restrict__ out)
{
    const int bx = blockIdx.x, by = blockIdx.y, b = blockIdx.z;
    const __half* A  = g_ps + (size_t)b * SS * SS;
    const __half* Bp = g_vt + (size_t)b * DD * SS;
    const int row0 = by * TM, col0 = bx * TN;
    const int ntiles = (row0 + TM) / TK;   // causal cap (>= 2)

    float acc[4][4][4];
#pragma unroll
    for (int i = 0; i < 4; i++)
#pragma unroll
        for (int j = 0; j < 4; j++)
#pragma unroll
            for (int q = 0; q < 4; q++) acc[i][j][q] = 0.f;

    gemm_core(A, row0, SS, Bp, col0, SS, ntiles, acc);

    float* C = out + (size_t)b * SS * DD;
    const int lane = threadIdx.x & 31, warp = threadIdx.x >> 5;
    const int wm = (warp & 1) << 6, wn = (warp >> 1) << 5;
    const int g = lane >> 2, tig = lane & 3;

#pragma unroll
    for (int mi = 0; mi < 4; mi++)
#pragma unroll
        for (int ni = 0; ni < 4; ni++) {
            const int n = col0 + wn + (ni << 3) + (tig << 1);
#pragma unroll
            for (int rr = 0; rr < 2; rr++) {
                const int m = row0 + wm + (mi << 4) + g + rr * 8;
                float2 v;
                v.x = acc[mi][ni][rr * 2 + 0];
                v.y = acc[mi][ni][rr * 2 + 1];
                *(float2*)(C + (size_t)m * DD + n) = v;
            }
        }
}

// ---------------------------------------------------------------------------
extern "C" void kernel_launch(void* const* d_in, const int* in_sizes, int n_in,
                              void* d_out, int out_size)
{
    const float* x  = (const float*)d_in[0];
    const float* Wq = (const float*)d_in[1];
    const float* bq = (const float*)d_in[2];
    const float* Wk = (const float*)d_in[3];
    const float* bk = (const float*)d_in[4];
    const float* Wv = (const float*)d_in[5];
    const float* bv = (const float*)d_in[6];
    float* out = (float*)d_out;

    cudaFuncSetAttribute(proj_kernel,   cudaFuncAttributeMaxDynamicSharedMemorySize, DYN_BYTES);
    cudaFuncSetAttribute(scores_kernel, cudaFuncAttributeMaxDynamicSharedMemorySize, DYN_BYTES);
    cudaFuncSetAttribute(pv_kernel,     cudaFuncAttributeMaxDynamicSharedMemorySize, DYN_BYTES);

    split_x_kernel<<<(MM * DD) / 256, 256>>>(x);
    split_w_kernel<<<dim3((DD * DD) / 256, 1, 3), 256>>>(Wq, Wk, Wv);
    proj_kernel<<<dim3(DD / TN, MM / TM, 3), 256, DYN_BYTES>>>(bq, bk, bv);
    scores_kernel<<<dim3(SS / TN, SS / TM, BB), 256, DYN_BYTES>>>();
    softmax_kernel<<<BB * SS, 256>>>();
    pv_kernel<<<dim3(DD / TN, SS / TM, BB), 256, DYN_BYTES>>>(out);
}

// round 13
// speedup vs baseline: 4.6150x; 1.4354x over previous
#include <cuda_runtime.h>
#include <cuda_fp16.h>
#include <cstdint>

// Problem constants
#define BB 4
#define SS 2048
#define DD 1024
#define MM (BB*SS)       // 8192

// GEMM tiling (8 warps, warp tile 64x32)
#define TM 128
#define TN 128
#define TK 64
#define AST 72           // TK + 8 pad: 144B row stride, ldmatrix conflict-free
#define ST 3             // cp.async stages (110.6KB smem -> 2 CTA/SM)

#define A_ELEMS (TM*AST)
#define STAGE_ELEMS (2*A_ELEMS)
#define DYN_BYTES (ST*STAGE_ELEMS*2)  // 110592 B dynamic smem

// ---------------------------------------------------------------------------
// Scratch.  All GEMMs run plain fp16, K=1024 (proj/scores) or causal-capped
// seq (PV).  Error budget (calibrated over R11/R12): ~6e-4 << 1e-3 gate.
// ---------------------------------------------------------------------------
__device__ __half g_xh[(size_t)MM * DD];        // x fp16
__device__ __half g_wq[(size_t)DD * DD];        // W fp16 (K-major = [out][in])
__device__ __half g_wk[(size_t)DD * DD];
__device__ __half g_wv[(size_t)DD * DD];
__device__ __half g_qs[(size_t)MM * DD];        // Q fp16
__device__ __half g_ks[(size_t)MM * DD];        // K fp16
__device__ __half g_vt[(size_t)BB * DD * SS];   // V^T fp16
__device__ float  g_sc[(size_t)BB * SS * SS];   // scores fp32
__device__ __half g_ps[(size_t)BB * SS * SS];   // softmax weights fp16

// ---------------------------------------------------------------------------
// Convert kernels (fp32 -> fp16)
// ---------------------------------------------------------------------------
__global__ __launch_bounds__(256) void conv_x_kernel(const float* __restrict__ x)
{
    size_t idx = (size_t)blockIdx.x * 256 + threadIdx.x;   // < MM*DD
    float2 v = ((const float2*)x)[idx];
    __half2 h; h.x = __float2half(v.x); h.y = __float2half(v.y);
    ((__half2*)g_xh)[idx] = h;
}

__global__ __launch_bounds__(256) void conv_w_kernel(
    const float* __restrict__ Wq, const float* __restrict__ Wk,
    const float* __restrict__ Wv)
{
    int z = blockIdx.z;
    size_t idx = (size_t)blockIdx.x * 256 + threadIdx.x;   // < DD*DD/2
    const float* W = (z == 0) ? Wq : (z == 1) ? Wk : Wv;
    __half* O = (z == 0) ? g_wq : (z == 1) ? g_wk : g_wv;
    float2 v = ((const float2*)W)[idx];
    __half2 h; h.x = __float2half(v.x); h.y = __float2half(v.y);
    ((__half2*)O)[idx] = h;
}

// ---------------------------------------------------------------------------
// GEMM core: C[128x128] = A * B^T, fp16 K-major, TK=64 tiles, 3-stage
// cp.async ring, register fragment pipeline carried across tile boundaries.
// Works for ntiles >= 2 (prologue prefetch of tile 2 is never consumed when
// ntiles == 2; callers guarantee those addresses are in-bounds).
// ---------------------------------------------------------------------------
#define LDSM_X4(r0, r1, r2, r3, addr) \
    asm volatile("ldmatrix.sync.aligned.m8n8.x4.shared.b16 {%0,%1,%2,%3}, [%4];" \
                 : "=r"(r0), "=r"(r1), "=r"(r2), "=r"(r3) : "r"(addr))

#define MMA16816(c, a, b0, b1)                                                \
    asm volatile(                                                             \
        "mma.sync.aligned.m16n8k16.row.col.f32.f16.f16.f32 "                  \
        "{%0,%1,%2,%3}, {%4,%5,%6,%7}, {%8,%9}, {%0,%1,%2,%3};\n"             \
        : "+f"((c)[0]), "+f"((c)[1]), "+f"((c)[2]), "+f"((c)[3])              \
        : "r"((a)[0]), "r"((a)[1]), "r"((a)[2]), "r"((a)[3]), "r"(b0), "r"(b1))

__device__ __forceinline__ void gemm_core(
    const __half* __restrict__ A, int row0, size_t lda,
    const __half* __restrict__ B, int col0, size_t ldb,
    int ntiles, float acc[4][4][4])
{
    extern __shared__ __align__(16) __half smem[];

    const int tid  = threadIdx.x;
    const int lane = tid & 31, warp = tid >> 5;
    const int wm = (warp & 1) << 6;       // 0/64
    const int wn = (warp >> 1) << 5;      // 0/32/64/96
    const int lr  = lane & 7;
    const int seg = lane >> 3;            // 0..3
    const int lrow = tid >> 3;            // loader row base 0..31
    const int lcol = (tid & 7) << 3;      // loader elem col 0..56

    uint32_t aBase[ST], bBase[ST];
#pragma unroll
    for (int s = 0; s < ST; s++) {
        aBase[s] = (uint32_t)__cvta_generic_to_shared(
            smem + s * STAGE_ELEMS + (wm + ((seg & 1) << 3) + lr) * AST + ((seg >> 1) << 3));
        bBase[s] = (uint32_t)__cvta_generic_to_shared(
            smem + s * STAGE_ELEMS + A_ELEMS + (wn + ((seg >> 1) << 3) + lr) * AST + ((seg & 1) << 3));
    }

    auto LDT = [&](int t) {
        const int ko = t * TK;
        __half* as = smem + (t % ST) * STAGE_ELEMS;
        __half* bs = as + A_ELEMS;
#pragma unroll
        for (int i = 0; i < 4; i++) {
            const int r = lrow + (i << 5);
            const void* sa = (const void*)(A + (size_t)(row0 + r) * lda + ko + lcol);
            uint32_t da = (uint32_t)__cvta_generic_to_shared(&as[r * AST + lcol]);
            asm volatile("cp.async.cg.shared.global [%0], [%1], 16;" :: "r"(da), "l"(sa));
            const void* sb = (const void*)(B + (size_t)(col0 + r) * ldb + ko + lcol);
            uint32_t db = (uint32_t)__cvta_generic_to_shared(&bs[r * AST + lcol]);
            asm volatile("cp.async.cg.shared.global [%0], [%1], 16;" :: "r"(db), "l"(sb));
        }
        asm volatile("cp.async.commit_group;" ::: "memory");
    };

    // Prologue: fill all 3 stages, arm k0 fragments of tile 0.
    LDT(0); LDT(1); LDT(2);
    asm volatile("cp.async.wait_group 2;" ::: "memory");
    __syncthreads();

    uint32_t af[2][4][4], bf[2][2][4];
#pragma unroll
    for (int mi = 0; mi < 4; mi++)
        LDSM_X4(af[0][mi][0], af[0][mi][1], af[0][mi][2], af[0][mi][3],
                aBase[0] + mi * (16 * AST * 2));
#pragma unroll
    for (int n2 = 0; n2 < 2; n2++)
        LDSM_X4(bf[0][n2][0], bf[0][n2][1], bf[0][n2][2], bf[0][n2][3],
                bBase[0] + n2 * (16 * AST * 2));

    for (int t = 0; t < ntiles; t++) {
        const int st = t % ST;
        const uint32_t ab = aBase[st], bb = bBase[st];

        // k-steps 0..2: prefetch next k-step fragments, mma current
#pragma unroll
        for (int kk = 0; kk < 3; kk++) {
            const int cur = kk & 1, nxt = cur ^ 1;
            const uint32_t ak = ab + (kk + 1) * 32;
            const uint32_t bk = bb + (kk + 1) * 32;
#pragma unroll
            for (int mi = 0; mi < 4; mi++)
                LDSM_X4(af[nxt][mi][0], af[nxt][mi][1], af[nxt][mi][2], af[nxt][mi][3],
                        ak + mi * (16 * AST * 2));
#pragma unroll
            for (int n2 = 0; n2 < 2; n2++)
                LDSM_X4(bf[nxt][n2][0], bf[nxt][n2][1], bf[nxt][n2][2], bf[nxt][n2][3],
                        bk + n2 * (16 * AST * 2));
#pragma unroll
            for (int mi = 0; mi < 4; mi++)
#pragma unroll
                for (int ni = 0; ni < 4; ni++)
                    MMA16816(acc[mi][ni], af[cur][mi],
                             bf[cur][ni >> 1][(ni & 1) << 1],
                             bf[cur][ni >> 1][((ni & 1) << 1) + 1]);
        }

        // k-step 3: publish stage t+1, preload its k0 fragments, then mma k3.
        if (t + 1 < ntiles) {
            if (t + 3 <= ntiles) { asm volatile("cp.async.wait_group 1;" ::: "memory"); }
            else                 { asm volatile("cp.async.wait_group 0;" ::: "memory"); }
            __syncthreads();
            const int sn = (t + 1) % ST;
#pragma unroll
            for (int mi = 0; mi < 4; mi++)
                LDSM_X4(af[0][mi][0], af[0][mi][1], af[0][mi][2], af[0][mi][3],
                        aBase[sn] + mi * (16 * AST * 2));
#pragma unroll
            for (int n2 = 0; n2 < 2; n2++)
                LDSM_X4(bf[0][n2][0], bf[0][n2][1], bf[0][n2][2], bf[0][n2][3],
                        bBase[sn] + n2 * (16 * AST * 2));
        }
#pragma unroll
        for (int mi = 0; mi < 4; mi++)
#pragma unroll
            for (int ni = 0; ni < 4; ni++)
                MMA16816(acc[mi][ni], af[1][mi],
                         bf[1][ni >> 1][(ni & 1) << 1],
                         bf[1][ni >> 1][((ni & 1) << 1) + 1]);

        if (t + 3 < ntiles) LDT(t + 3);
    }
    __syncthreads();
}

// ---------------------------------------------------------------------------
// Kernel: QKV projections (z = 0/1/2 -> Q/K/V), fp16 K=1024.
// ---------------------------------------------------------------------------
__global__ __launch_bounds__(256, 2) void proj_kernel(
    const float* __restrict__ bq, const float* __restrict__ bk,
    const float* __restrict__ bv)
{
    const int z = blockIdx.z;
    const __half* W   = (z == 0) ? g_wq : (z == 1) ? g_wk : g_wv;
    const float* bias = (z == 0) ? bq   : (z == 1) ? bk   : bv;
    const int row0 = blockIdx.y * TM, col0 = blockIdx.x * TN;

    float acc[4][4][4];
#pragma unroll
    for (int i = 0; i < 4; i++)
#pragma unroll
        for (int j = 0; j < 4; j++)
#pragma unroll
            for (int q = 0; q < 4; q++) acc[i][j][q] = 0.f;

    gemm_core(g_xh, row0, DD, W, col0, DD, DD / TK, acc);

    const int lane = threadIdx.x & 31, warp = threadIdx.x >> 5;
    const int wm = (warp & 1) << 6, wn = (warp >> 1) << 5;
    const int g = lane >> 2, tig = lane & 3;

#pragma unroll
    for (int mi = 0; mi < 4; mi++)
#pragma unroll
        for (int ni = 0; ni < 4; ni++) {
            const int n = col0 + wn + (ni << 3) + (tig << 1);
            const float b0 = bias[n], b1 = bias[n + 1];
#pragma unroll
            for (int rr = 0; rr < 2; rr++) {
                const int m = row0 + wm + (mi << 4) + g + rr * 8;
                __half h0 = __float2half(acc[mi][ni][rr * 2 + 0] + b0);
                __half h1 = __float2half(acc[mi][ni][rr * 2 + 1] + b1);
                if (z < 2) {           // Q / K: plain fp16 row-major
                    __half* r = ((z == 0) ? g_qs : g_ks) + (size_t)m * DD + n;
                    __half2 th; th.x = h0; th.y = h1;
                    *(__half2*)r = th;
                } else {               // V: transposed into g_vt[b][d][S]
                    const int b = m >> 11, s = m & (SS - 1);
                    g_vt[((size_t)b * DD + n) * SS + s]     = h0;
                    g_vt[((size_t)b * DD + n + 1) * SS + s] = h1;
                }
            }
        }
}

// ---------------------------------------------------------------------------
// Kernel: scores = Q K^T / sqrt(D), fp16 K=1024; upper blocks skipped.
// ---------------------------------------------------------------------------
__global__ __launch_bounds__(256, 2) void scores_kernel()
{
    const int bx = blockIdx.x, by = blockIdx.y, b = blockIdx.z;
    if (bx > by) return;
    const __half* A  = g_qs + (size_t)b * SS * DD;
    const __half* Bp = g_ks + (size_t)b * SS * DD;
    const int row0 = by * TM, col0 = bx * TN;

    float acc[4][4][4];
#pragma unroll
    for (int i = 0; i < 4; i++)
#pragma unroll
        for (int j = 0; j < 4; j++)
#pragma unroll
            for (int q = 0; q < 4; q++) acc[i][j][q] = 0.f;

    gemm_core(A, row0, DD, Bp, col0, DD, DD / TK, acc);

    float* C = g_sc + (size_t)b * SS * SS;
    const int lane = threadIdx.x & 31, warp = threadIdx.x >> 5;
    const int wm = (warp & 1) << 6, wn = (warp >> 1) << 5;
    const int g = lane >> 2, tig = lane & 3;

#pragma unroll
    for (int mi = 0; mi < 4; mi++)
#pragma unroll
        for (int ni = 0; ni < 4; ni++) {
            const int n = col0 + wn + (ni << 3) + (tig << 1);
#pragma unroll
            for (int rr = 0; rr < 2; rr++) {
                const int m = row0 + wm + (mi << 4) + g + rr * 8;
                float2 v;
                v.x = acc[mi][ni][rr * 2 + 0] * 0.03125f;
                v.y = acc[mi][ni][rr * 2 + 1] * 0.03125f;
                *(float2*)(C + (size_t)m * SS + n) = v;
            }
        }
}

// ---------------------------------------------------------------------------
// Kernel: causal row softmax; writes plain fp16 weights, zero fill.
// ---------------------------------------------------------------------------
__global__ __launch_bounds__(256) void softmax_kernel()
{
    const int row = blockIdx.x;
    const int b = row >> 11;
    const int i = row & (SS - 1);
    const float* p = g_sc + (size_t)b * SS * SS + (size_t)i * SS;
    __half* o = g_ps + (size_t)b * SS * SS + (size_t)i * SS;
    const int len = i + 1;
    const int tid = threadIdx.x;
    const int lane = tid & 31, wid = tid >> 5;
    __shared__ float red[8];

    float m = __int_as_float(0xff800000);
    float xv[8];
#pragma unroll
    for (int jj = 0; jj < 8; jj++) {
        int j = tid + jj * 256;
        xv[jj] = (j < len) ? p[j] : __int_as_float(0xff800000);
        m = fmaxf(m, xv[jj]);
    }
#pragma unroll
    for (int off = 16; off; off >>= 1) m = fmaxf(m, __shfl_xor_sync(0xffffffffu, m, off));
    if (lane == 0) red[wid] = m;
    __syncthreads();
    if (tid == 0) {
        float mm = red[0];
#pragma unroll
        for (int w = 1; w < 8; w++) mm = fmaxf(mm, red[w]);
        red[0] = mm;
    }
    __syncthreads();
    m = red[0];
    __syncthreads();

    float s = 0.f;
    float ev[8];
#pragma unroll
    for (int jj = 0; jj < 8; jj++) {
        int j = tid + jj * 256;
        ev[jj] = (j < len) ? __expf(xv[jj] - m) : 0.f;
        s += ev[jj];
    }
#pragma unroll
    for (int off = 16; off; off >>= 1) s += __shfl_xor_sync(0xffffffffu, s, off);
    if (lane == 0) red[wid] = s;
    __syncthreads();
    if (tid == 0) {
        float ss = 0.f;
#pragma unroll
        for (int w = 0; w < 8; w++) ss += red[w];
        red[0] = ss;
    }
    __syncthreads();
    const float inv = 1.f / red[0];

#pragma unroll
    for (int jj = 0; jj < 8; jj++) {
        int j = tid + jj * 256;
        o[j] = __float2half(ev[jj] * inv);     // 0 for j > i
    }
}

// ---------------------------------------------------------------------------
// Kernel: out = P V, fp16, K capped at the diagonal of this block-row.
// ---------------------------------------------------------------------------
__global__ __launch_bounds__(256, 2) void pv_kernel(float* __restrict__ out)
{
    const int bx = blockIdx.x, by = blockIdx.y, b = blockIdx.z;
    const __half* A  = g_ps + (size_t)b * SS * SS;
    const __half* Bp = g_vt + (size_t)b * DD * SS;
    const int row0 = by * TM, col0 = bx * TN;
    const int ntiles = (row0 + TM) / TK;   // causal cap (>= 2)

    float acc[4][4][4];
#pragma unroll
    for (int i = 0; i < 4; i++)
#pragma unroll
        for (int j = 0; j < 4; j++)
#pragma unroll
            for (int q = 0; q < 4; q++) acc[i][j][q] = 0.f;

    gemm_core(A, row0, SS, Bp, col0, SS, ntiles, acc);

    float* C = out + (size_t)b * SS * DD;
    const int lane = threadIdx.x & 31, warp = threadIdx.x >> 5;
    const int wm = (warp & 1) << 6, wn = (warp >> 1) << 5;
    const int g = lane >> 2, tig = lane & 3;

#pragma unroll
    for (int mi = 0; mi < 4; mi++)
#pragma unroll
        for (int ni = 0; ni < 4; ni++) {
            const int n = col0 + wn + (ni << 3) + (tig << 1);
#pragma unroll
            for (int rr = 0; rr < 2; rr++) {
                const int m = row0 + wm + (mi << 4) + g + rr * 8;
                float2 v;
                v.x = acc[mi][ni][rr * 2 + 0];
                v.y = acc[mi][ni][rr * 2 + 1];
                *(float2*)(C + (size_t)m * DD + n) = v;
            }
        }
}

// ---------------------------------------------------------------------------
extern "C" void kernel_launch(void* const* d_in, const int* in_sizes, int n_in,
                              void* d_out, int out_size)
{
    const float* x  = (const float*)d_in[0];
    const float* Wq = (const float*)d_in[1];
    const float* bq = (const float*)d_in[2];
    const float* Wk = (const float*)d_in[3];
    const float* bk = (const float*)d_in[4];
    const float* Wv = (const float*)d_in[5];
    const float* bv = (const float*)d_in[6];
    float* out = (float*)d_out;

    cudaFuncSetAttribute(proj_kernel,   cudaFuncAttributeMaxDynamicSharedMemorySize, DYN_BYTES);
    cudaFuncSetAttribute(scores_kernel, cudaFuncAttributeMaxDynamicSharedMemorySize, DYN_BYTES);
    cudaFuncSetAttribute(pv_kernel,     cudaFuncAttributeMaxDynamicSharedMemorySize, DYN_BYTES);

    conv_x_kernel<<<(MM * DD / 2) / 256, 256>>>(x);
    conv_w_kernel<<<dim3((DD * DD / 2) / 256, 1, 3), 256>>>(Wq, Wk, Wv);
    proj_kernel<<<dim3(DD / TN, MM / TM, 3), 256, DYN_BYTES>>>(bq, bk, bv);
    scores_kernel<<<dim3(SS / TN, SS / TM, BB), 256, DYN_BYTES>>>();
    softmax_kernel<<<BB * SS, 256>>>();
    pv_kernel<<<dim3(DD / TN, SS / TM, BB), 256, DYN_BYTES>>>(out);
}

// round 14
// speedup vs baseline: 4.7618x; 1.0318x over previous
#include <cuda_runtime.h>
#include <cuda_fp16.h>
#include <cstdint>

// Problem constants
#define BB 4
#define SS 2048
#define DD 1024
#define MM (BB*SS)       // 8192

// GEMM tiling (8 warps, warp tile 64x32)
#define TM 128
#define TN 128
#define TK 64
#define AST 72           // TK + 8 pad: 144B row stride, ldmatrix conflict-free
#define ST 3             // cp.async stages (110.6KB smem -> 2 CTA/SM)

#define A_ELEMS (TM*AST)
#define STAGE_ELEMS (2*A_ELEMS)
#define DYN_BYTES (ST*STAGE_ELEMS*2)  // 110592 B dynamic smem

// ---------------------------------------------------------------------------
// Scratch.  All GEMMs plain fp16 (error budget calibrated ~5.9e-4 < 1e-3).
// ---------------------------------------------------------------------------
__device__ __half g_xh[(size_t)MM * DD];        // x fp16
__device__ __half g_wq[(size_t)DD * DD];        // W fp16 (K-major = [out][in])
__device__ __half g_wk[(size_t)DD * DD];
__device__ __half g_wv[(size_t)DD * DD];
__device__ __half g_qs[(size_t)MM * DD];        // Q fp16
__device__ __half g_ks[(size_t)MM * DD];        // K fp16
__device__ __half g_vt[(size_t)BB * DD * SS];   // V^T fp16
__device__ float  g_sc[(size_t)BB * SS * SS];   // scores fp32
__device__ __half g_ps[(size_t)BB * SS * SS];   // softmax weights fp16

// ---------------------------------------------------------------------------
// Convert kernels (fp32 -> fp16)
// ---------------------------------------------------------------------------
__global__ __launch_bounds__(256) void conv_x_kernel(const float* __restrict__ x)
{
    size_t idx = (size_t)blockIdx.x * 256 + threadIdx.x;   // < MM*DD/2
    float2 v = ((const float2*)x)[idx];
    __half2 h; h.x = __float2half(v.x); h.y = __float2half(v.y);
    ((__half2*)g_xh)[idx] = h;
}

__global__ __launch_bounds__(256) void conv_w_kernel(
    const float* __restrict__ Wq, const float* __restrict__ Wk,
    const float* __restrict__ Wv)
{
    int z = blockIdx.z;
    size_t idx = (size_t)blockIdx.x * 256 + threadIdx.x;   // < DD*DD/2
    const float* W = (z == 0) ? Wq : (z == 1) ? Wk : Wv;
    __half* O = (z == 0) ? g_wq : (z == 1) ? g_wk : g_wv;
    float2 v = ((const float2*)W)[idx];
    __half2 h; h.x = __float2half(v.x); h.y = __float2half(v.y);
    ((__half2*)O)[idx] = h;
}

// ---------------------------------------------------------------------------
// GEMM core: C[128x128] = A * B^T, fp16 K-major, TK=64 tiles, 3-stage
// cp.async ring, register fragment pipeline carried across tile boundaries.
// Works for ntiles >= 2.  Ends with __syncthreads() (smem reusable after).
// ---------------------------------------------------------------------------
#define LDSM_X4(r0, r1, r2, r3, addr) \
    asm volatile("ldmatrix.sync.aligned.m8n8.x4.shared.b16 {%0,%1,%2,%3}, [%4];" \
                 : "=r"(r0), "=r"(r1), "=r"(r2), "=r"(r3) : "r"(addr))

#define MMA16816(c, a, b0, b1)                                                \
    asm volatile(                                                             \
        "mma.sync.aligned.m16n8k16.row.col.f32.f16.f16.f32 "                  \
        "{%0,%1,%2,%3}, {%4,%5,%6,%7}, {%8,%9}, {%0,%1,%2,%3};\n"             \
        : "+f"((c)[0]), "+f"((c)[1]), "+f"((c)[2]), "+f"((c)[3])              \
        : "r"((a)[0]), "r"((a)[1]), "r"((a)[2]), "r"((a)[3]), "r"(b0), "r"(b1))

__device__ __forceinline__ void gemm_core(
    const __half* __restrict__ A, int row0, size_t lda,
    const __half* __restrict__ B, int col0, size_t ldb,
    int ntiles, float acc[4][4][4])
{
    extern __shared__ __align__(16) __half smem[];

    const int tid  = threadIdx.x;
    const int lane = tid & 31, warp = tid >> 5;
    const int wm = (warp & 1) << 6;       // 0/64
    const int wn = (warp >> 1) << 5;      // 0/32/64/96
    const int lr  = lane & 7;
    const int seg = lane >> 3;            // 0..3
    const int lrow = tid >> 3;            // loader row base 0..31
    const int lcol = (tid & 7) << 3;      // loader elem col 0..56

    uint32_t aBase[ST], bBase[ST];
#pragma unroll
    for (int s = 0; s < ST; s++) {
        aBase[s] = (uint32_t)__cvta_generic_to_shared(
            smem + s * STAGE_ELEMS + (wm + ((seg & 1) << 3) + lr) * AST + ((seg >> 1) << 3));
        bBase[s] = (uint32_t)__cvta_generic_to_shared(
            smem + s * STAGE_ELEMS + A_ELEMS + (wn + ((seg >> 1) << 3) + lr) * AST + ((seg & 1) << 3));
    }

    auto LDT = [&](int t) {
        const int ko = t * TK;
        __half* as = smem + (t % ST) * STAGE_ELEMS;
        __half* bs = as + A_ELEMS;
#pragma unroll
        for (int i = 0; i < 4; i++) {
            const int r = lrow + (i << 5);
            const void* sa = (const void*)(A + (size_t)(row0 + r) * lda + ko + lcol);
            uint32_t da = (uint32_t)__cvta_generic_to_shared(&as[r * AST + lcol]);
            asm volatile("cp.async.cg.shared.global [%0], [%1], 16;" :: "r"(da), "l"(sa));
            const void* sb = (const void*)(B + (size_t)(col0 + r) * ldb + ko + lcol);
            uint32_t db = (uint32_t)__cvta_generic_to_shared(&bs[r * AST + lcol]);
            asm volatile("cp.async.cg.shared.global [%0], [%1], 16;" :: "r"(db), "l"(sb));
        }
        asm volatile("cp.async.commit_group;" ::: "memory");
    };

    // Prologue: fill all 3 stages, arm k0 fragments of tile 0.
    LDT(0); LDT(1); LDT(2);
    asm volatile("cp.async.wait_group 2;" ::: "memory");
    __syncthreads();

    uint32_t af[2][4][4], bf[2][2][4];
#pragma unroll
    for (int mi = 0; mi < 4; mi++)
        LDSM_X4(af[0][mi][0], af[0][mi][1], af[0][mi][2], af[0][mi][3],
                aBase[0] + mi * (16 * AST * 2));
#pragma unroll
    for (int n2 = 0; n2 < 2; n2++)
        LDSM_X4(bf[0][n2][0], bf[0][n2][1], bf[0][n2][2], bf[0][n2][3],
                bBase[0] + n2 * (16 * AST * 2));

    for (int t = 0; t < ntiles; t++) {
        const int st = t % ST;
        const uint32_t ab = aBase[st], bb = bBase[st];

        // k-steps 0..2: prefetch next k-step fragments, mma current
#pragma unroll
        for (int kk = 0; kk < 3; kk++) {
            const int cur = kk & 1, nxt = cur ^ 1;
            const uint32_t ak = ab + (kk + 1) * 32;
            const uint32_t bk = bb + (kk + 1) * 32;
#pragma unroll
            for (int mi = 0; mi < 4; mi++)
                LDSM_X4(af[nxt][mi][0], af[nxt][mi][1], af[nxt][mi][2], af[nxt][mi][3],
                        ak + mi * (16 * AST * 2));
#pragma unroll
            for (int n2 = 0; n2 < 2; n2++)
                LDSM_X4(bf[nxt][n2][0], bf[nxt][n2][1], bf[nxt][n2][2], bf[nxt][n2][3],
                        bk + n2 * (16 * AST * 2));
#pragma unroll
            for (int mi = 0; mi < 4; mi++)
#pragma unroll
                for (int ni = 0; ni < 4; ni++)
                    MMA16816(acc[mi][ni], af[cur][mi],
                             bf[cur][ni >> 1][(ni & 1) << 1],
                             bf[cur][ni >> 1][((ni & 1) << 1) + 1]);
        }

        // k-step 3: publish stage t+1, preload its k0 fragments, then mma k3.
        if (t + 1 < ntiles) {
            if (t + 3 <= ntiles) { asm volatile("cp.async.wait_group 1;" ::: "memory"); }
            else                 { asm volatile("cp.async.wait_group 0;" ::: "memory"); }
            __syncthreads();
            const int sn = (t + 1) % ST;
#pragma unroll
            for (int mi = 0; mi < 4; mi++)
                LDSM_X4(af[0][mi][0], af[0][mi][1], af[0][mi][2], af[0][mi][3],
                        aBase[sn] + mi * (16 * AST * 2));
#pragma unroll
            for (int n2 = 0; n2 < 2; n2++)
                LDSM_X4(bf[0][n2][0], bf[0][n2][1], bf[0][n2][2], bf[0][n2][3],
                        bBase[sn] + n2 * (16 * AST * 2));
        }
#pragma unroll
        for (int mi = 0; mi < 4; mi++)
#pragma unroll
            for (int ni = 0; ni < 4; ni++)
                MMA16816(acc[mi][ni], af[1][mi],
                         bf[1][ni >> 1][(ni & 1) << 1],
                         bf[1][ni >> 1][((ni & 1) << 1) + 1]);

        if (t + 3 < ntiles) LDT(t + 3);
    }
    __syncthreads();
}

// ---------------------------------------------------------------------------
// Kernel: QKV projections (z = 0/1/2 -> Q/K/V), fp16 K=1024.
// V epilogue: smem-staged transpose -> coalesced half2 row writes to g_vt.
// ---------------------------------------------------------------------------
#define TST 136   // transpose smem stride (halfs): 272B rows, conflict-benign

__global__ __launch_bounds__(256, 2) void proj_kernel(
    const float* __restrict__ bq, const float* __restrict__ bk,
    const float* __restrict__ bv)
{
    extern __shared__ __align__(16) __half smem[];
    const int z = blockIdx.z;
    const __half* W   = (z == 0) ? g_wq : (z == 1) ? g_wk : g_wv;
    const float* bias = (z == 0) ? bq   : (z == 1) ? bk   : bv;
    const int row0 = blockIdx.y * TM, col0 = blockIdx.x * TN;

    float acc[4][4][4];
#pragma unroll
    for (int i = 0; i < 4; i++)
#pragma unroll
        for (int j = 0; j < 4; j++)
#pragma unroll
            for (int q = 0; q < 4; q++) acc[i][j][q] = 0.f;

    gemm_core(g_xh, row0, DD, W, col0, DD, DD / TK, acc);

    const int tid = threadIdx.x;
    const int lane = tid & 31, warp = tid >> 5;
    const int wm = (warp & 1) << 6, wn = (warp >> 1) << 5;
    const int g = lane >> 2, tig = lane & 3;

    if (z < 2) {               // Q / K: plain fp16 row-major
        __half* base = (z == 0) ? g_qs : g_ks;
#pragma unroll
        for (int mi = 0; mi < 4; mi++)
#pragma unroll
            for (int ni = 0; ni < 4; ni++) {
                const int n = col0 + wn + (ni << 3) + (tig << 1);
                const float b0 = bias[n], b1 = bias[n + 1];
#pragma unroll
                for (int rr = 0; rr < 2; rr++) {
                    const int m = row0 + wm + (mi << 4) + g + rr * 8;
                    __half2 th;
                    th.x = __float2half(acc[mi][ni][rr * 2 + 0] + b0);
                    th.y = __float2half(acc[mi][ni][rr * 2 + 1] + b1);
                    *(__half2*)(base + (size_t)m * DD + n) = th;
                }
            }
    } else {                   // V: transpose via smem, then coalesced writes
        __half* st = smem;     // gemm_core ended with __syncthreads: smem free
#pragma unroll
        for (int mi = 0; mi < 4; mi++)
#pragma unroll
            for (int ni = 0; ni < 4; ni++) {
                const int nl = wn + (ni << 3) + (tig << 1);
                const float b0 = bias[col0 + nl], b1 = bias[col0 + nl + 1];
#pragma unroll
                for (int rr = 0; rr < 2; rr++) {
                    const int ml = wm + (mi << 4) + g + rr * 8;
                    st[nl * TST + ml]       = __float2half(acc[mi][ni][rr * 2 + 0] + b0);
                    st[(nl + 1) * TST + ml] = __float2half(acc[mi][ni][rr * 2 + 1] + b1);
                }
            }
        __syncthreads();
        const int b = row0 >> 11, s0 = row0 & (SS - 1);
#pragma unroll
        for (int rep = 0; rep < 32; rep++) {
            const int idx = rep * 256 + tid;     // 0..8191 half2 slots
            const int d = idx >> 6;              // 0..127 (n_local)
            const int c = (idx & 63) << 1;       // 0..126 (m_local, even)
            __half2 v = *(__half2*)&st[d * TST + c];
            *(__half2*)&g_vt[((size_t)b * DD + col0 + d) * SS + s0 + c] = v;
        }
    }
}

// ---------------------------------------------------------------------------
// Kernel: scores = Q K^T / sqrt(D), fp16 K=1024.  Compact triangular grid:
// blockIdx.x in [0,136) decodes to (by, bx) with bx <= by.
// ---------------------------------------------------------------------------
__global__ __launch_bounds__(256, 2) void scores_kernel()
{
    const int t = blockIdx.x, b = blockIdx.z;
    int by = (int)((sqrtf(8.f * t + 1.f) - 1.f) * 0.5f);
    while ((by + 1) * (by + 2) / 2 <= t) by++;
    while (by * (by + 1) / 2 > t) by--;
    const int bx = t - by * (by + 1) / 2;

    const __half* A  = g_qs + (size_t)b * SS * DD;
    const __half* Bp = g_ks + (size_t)b * SS * DD;
    const int row0 = by * TM, col0 = bx * TN;

    float acc[4][4][4];
#pragma unroll
    for (int i = 0; i < 4; i++)
#pragma unroll
        for (int j = 0; j < 4; j++)
#pragma unroll
            for (int q = 0; q < 4; q++) acc[i][j][q] = 0.f;

    gemm_core(A, row0, DD, Bp, col0, DD, DD / TK, acc);

    float* C = g_sc + (size_t)b * SS * SS;
    const int lane = threadIdx.x & 31, warp = threadIdx.x >> 5;
    const int wm = (warp & 1) << 6, wn = (warp >> 1) << 5;
    const int g = lane >> 2, tig = lane & 3;

#pragma unroll
    for (int mi = 0; mi < 4; mi++)
#pragma unroll
        for (int ni = 0; ni < 4; ni++) {
            const int n = col0 + wn + (ni << 3) + (tig << 1);
#pragma unroll
            for (int rr = 0; rr < 2; rr++) {
                const int m = row0 + wm + (mi << 4) + g + rr * 8;
                float2 v;
                v.x = acc[mi][ni][rr * 2 + 0] * 0.03125f;
                v.y = acc[mi][ni][rr * 2 + 1] * 0.03125f;
                *(float2*)(C + (size_t)m * SS + n) = v;
            }
        }
}

// ---------------------------------------------------------------------------
// Kernel: causal row softmax, vectorized (float4 in, half2 out).
// Above-diagonal score blocks are never written (zero-init device mem) and
// are masked before use, so unconditional vector loads are safe.
// ---------------------------------------------------------------------------
__global__ __launch_bounds__(256) void softmax_kernel()
{
    const int row = blockIdx.x;
    const int b = row >> 11;
    const int i = row & (SS - 1);
    const float* p = g_sc + (size_t)b * SS * SS + (size_t)i * SS;
    __half* o = g_ps + (size_t)b * SS * SS + (size_t)i * SS;
    const int len = i + 1;
    const int tid = threadIdx.x;
    const int lane = tid & 31, wid = tid >> 5;
    __shared__ float red[8];

    // load 8 elems per thread: two float4 groups at j = tid*4 and 1024+tid*4
    float4 xq[2];
    xq[0] = ((const float4*)p)[tid];
    xq[1] = ((const float4*)p)[tid + 256];
    float xv[8];
    *(float4*)&xv[0] = xq[0];
    *(float4*)&xv[4] = xq[1];
    int jb[2] = { tid * 4, 1024 + tid * 4 };

    float m = __int_as_float(0xff800000);
#pragma unroll
    for (int gr = 0; gr < 2; gr++)
#pragma unroll
        for (int e = 0; e < 4; e++) {
            bool ok = jb[gr] + e < len;
            if (ok) m = fmaxf(m, xv[gr * 4 + e]);
        }
#pragma unroll
    for (int off = 16; off; off >>= 1) m = fmaxf(m, __shfl_xor_sync(0xffffffffu, m, off));
    if (lane == 0) red[wid] = m;
    __syncthreads();
    if (tid == 0) {
        float mm = red[0];
#pragma unroll
        for (int w = 1; w < 8; w++) mm = fmaxf(mm, red[w]);
        red[0] = mm;
    }
    __syncthreads();
    m = red[0];
    __syncthreads();

    float s = 0.f;
    float ev[8];
#pragma unroll
    for (int gr = 0; gr < 2; gr++)
#pragma unroll
        for (int e = 0; e < 4; e++) {
            int k = gr * 4 + e;
            ev[k] = (jb[gr] + e < len) ? __expf(xv[k] - m) : 0.f;
            s += ev[k];
        }
#pragma unroll
    for (int off = 16; off; off >>= 1) s += __shfl_xor_sync(0xffffffffu, s, off);
    if (lane == 0) red[wid] = s;
    __syncthreads();
    if (tid == 0) {
        float ss = 0.f;
#pragma unroll
        for (int w = 0; w < 8; w++) ss += red[w];
        red[0] = ss;
    }
    __syncthreads();
    const float inv = 1.f / red[0];

    __half2* o2 = (__half2*)o;
#pragma unroll
    for (int gr = 0; gr < 2; gr++) {
        __half2 h0, h1;
        h0.x = __float2half(ev[gr * 4 + 0] * inv);
        h0.y = __float2half(ev[gr * 4 + 1] * inv);
        h1.x = __float2half(ev[gr * 4 + 2] * inv);
        h1.y = __float2half(ev[gr * 4 + 3] * inv);
        o2[gr * 512 + tid * 2]     = h0;
        o2[gr * 512 + tid * 2 + 1] = h1;
    }
}

// ---------------------------------------------------------------------------
// Kernel: out = P V, fp16, K capped at the diagonal; longest rows first.
// ---------------------------------------------------------------------------
__global__ __launch_bounds__(256, 2) void pv_kernel(float* __restrict__ out)
{
    const int bx = blockIdx.x, by = 15 - blockIdx.y, b = blockIdx.z;
    const __half* A  = g_ps + (size_t)b * SS * SS;
    const __half* Bp = g_vt + (size_t)b * DD * SS;
    const int row0 = by * TM, col0 = bx * TN;
    const int ntiles = (row0 + TM) / TK;   // causal cap (>= 2)

    float acc[4][4][4];
#pragma unroll
    for (int i = 0; i < 4; i++)
#pragma unroll
        for (int j = 0; j < 4; j++)
#pragma unroll
            for (int q = 0; q < 4; q++) acc[i][j][q] = 0.f;

    gemm_core(A, row0, SS, Bp, col0, SS, ntiles, acc);

    float* C = out + (size_t)b * SS * DD;
    const int lane = threadIdx.x & 31, warp = threadIdx.x >> 5;
    const int wm = (warp & 1) << 6, wn = (warp >> 1) << 5;
    const int g = lane >> 2, tig = lane & 3;

#pragma unroll
    for (int mi = 0; mi < 4; mi++)
#pragma unroll
        for (int ni = 0; ni < 4; ni++) {
            const int n = col0 + wn + (ni << 3) + (tig << 1);
#pragma unroll
            for (int rr = 0; rr < 2; rr++) {
                const int m = row0 + wm + (mi << 4) + g + rr * 8;
                float2 v;
                v.x = acc[mi][ni][rr * 2 + 0];
                v.y = acc[mi][ni][rr * 2 + 1];
                *(float2*)(C + (size_t)m * DD + n) = v;
            }
        }
}

// ---------------------------------------------------------------------------
extern "C" void kernel_launch(void* const* d_in, const int* in_sizes, int n_in,
                              void* d_out, int out_size)
{
    const float* x  = (const float*)d_in[0];
    const float* Wq = (const float*)d_in[1];
    const float* bq = (const float*)d_in[2];
    const float* Wk = (const float*)d_in[3];
    const float* bk = (const float*)d_in[4];
    const float* Wv = (const float*)d_in[5];
    const float* bv = (const float*)d_in[6];
    float* out = (float*)d_out;

    cudaFuncSetAttribute(proj_kernel,   cudaFuncAttributeMaxDynamicSharedMemorySize, DYN_BYTES);
    cudaFuncSetAttribute(scores_kernel, cudaFuncAttributeMaxDynamicSharedMemorySize, DYN_BYTES);
    cudaFuncSetAttribute(pv_kernel,     cudaFuncAttributeMaxDynamicSharedMemorySize, DYN_BYTES);

    conv_x_kernel<<<(MM * DD / 2) / 256, 256>>>(x);
    conv_w_kernel<<<dim3((DD * DD / 2) / 256, 1, 3), 256>>>(Wq, Wk, Wv);
    proj_kernel<<<dim3(DD / TN, MM / TM, 3), 256, DYN_BYTES>>>(bq, bk, bv);
    scores_kernel<<<dim3(136, 1, BB), 256, DYN_BYTES>>>();
    softmax_kernel<<<BB * SS, 256>>>();
    pv_kernel<<<dim3(DD / TN, SS / TM, BB), 256, DYN_BYTES>>>(out);
}

// round 16
// speedup vs baseline: 4.7890x; 1.0057x over previous
#include <cuda_runtime.h>
#include <cuda_fp16.h>
#include <cstdint>

// Problem constants
#define BB 4
#define SS 2048
#define DD 1024
#define MM (BB*SS)       // 8192

// GEMM tiling (8 warps, warp tile 64x32)
#define TM 128
#define TN 128
#define TK 64
#define AST 72           // TK + 8 pad: 144B row stride, ldmatrix conflict-free
#define ST 3             // cp.async stages (110.6KB smem -> 2 CTA/SM)

#define A_ELEMS (TM*AST)
#define STAGE_ELEMS (2*A_ELEMS)
#define DYN_BYTES (ST*STAGE_ELEMS*2)  // 110592 B dynamic smem

// ---------------------------------------------------------------------------
// Scratch.  All GEMMs plain fp16 (error budget calibrated ~5.9e-4 < 1e-3).
// ---------------------------------------------------------------------------
__device__ __half g_xh[(size_t)MM * DD];        // x fp16
__device__ __half g_wq[(size_t)DD * DD];        // W fp16 (K-major = [out][in])
__device__ __half g_wk[(size_t)DD * DD];
__device__ __half g_wv[(size_t)DD * DD];
__device__ __half g_qs[(size_t)MM * DD];        // Q fp16
__device__ __half g_ks[(size_t)MM * DD];        // K fp16
__device__ __half g_vt[(size_t)BB * DD * SS];   // V^T fp16
__device__ float  g_sc[(size_t)BB * SS * SS];   // scores fp32
__device__ __half g_ps[(size_t)BB * SS * SS];   // softmax weights fp16

// ---------------------------------------------------------------------------
// Convert kernels (fp32 -> fp16)
// ---------------------------------------------------------------------------
__global__ __launch_bounds__(256) void conv_x_kernel(const float* __restrict__ x)
{
    size_t idx = (size_t)blockIdx.x * 256 + threadIdx.x;   // < MM*DD/2
    float2 v = ((const float2*)x)[idx];
    __half2 h; h.x = __float2half(v.x); h.y = __float2half(v.y);
    ((__half2*)g_xh)[idx] = h;
}

__global__ __launch_bounds__(256) void conv_w_kernel(
    const float* __restrict__ Wq, const float* __restrict__ Wk,
    const float* __restrict__ Wv)
{
    int z = blockIdx.z;
    size_t idx = (size_t)blockIdx.x * 256 + threadIdx.x;   // < DD*DD/2
    const float* W = (z == 0) ? Wq : (z == 1) ? Wk : Wv;
    __half* O = (z == 0) ? g_wq : (z == 1) ? g_wk : g_wv;
    float2 v = ((const float2*)W)[idx];
    __half2 h; h.x = __float2half(v.x); h.y = __float2half(v.y);
    ((__half2*)O)[idx] = h;
}

// ---------------------------------------------------------------------------
// GEMM core: C[128x128] = A * B^T, fp16 K-major, TK=64 tiles, 3-stage
// cp.async ring, register fragment pipeline carried across tile boundaries.
// Works for ntiles >= 2.  Ends with __syncthreads() (smem reusable after).
// ---------------------------------------------------------------------------
#define LDSM_X4(r0, r1, r2, r3, addr) \
    asm volatile("ldmatrix.sync.aligned.m8n8.x4.shared.b16 {%0,%1,%2,%3}, [%4];" \
                 : "=r"(r0), "=r"(r1), "=r"(r2), "=r"(r3) : "r"(addr))

#define MMA16816(c, a, b0, b1)                                                \
    asm volatile(                                                             \
        "mma.sync.aligned.m16n8k16.row.col.f32.f16.f16.f32 "                  \
        "{%0,%1,%2,%3}, {%4,%5,%6,%7}, {%8,%9}, {%0,%1,%2,%3};\n"             \
        : "+f"((c)[0]), "+f"((c)[1]), "+f"((c)[2]), "+f"((c)[3])              \
        : "r"((a)[0]), "r"((a)[1]), "r"((a)[2]), "r"((a)[3]), "r"(b0), "r"(b1))

__device__ __forceinline__ void gemm_core(
    const __half* __restrict__ A, int row0, size_t lda,
    const __half* __restrict__ B, int col0, size_t ldb,
    int ntiles, float acc[4][4][4])
{
    extern __shared__ __align__(16) __half smem[];

    const int tid  = threadIdx.x;
    const int lane = tid & 31, warp = tid >> 5;
    const int wm = (warp & 1) << 6;       // 0/64
    const int wn = (warp >> 1) << 5;      // 0/32/64/96
    const int lr  = lane & 7;
    const int seg = lane >> 3;            // 0..3
    const int lrow = tid >> 3;            // loader row base 0..31
    const int lcol = (tid & 7) << 3;      // loader elem col 0..56

    uint32_t aBase[ST], bBase[ST];
#pragma unroll
    for (int s = 0; s < ST; s++) {
        aBase[s] = (uint32_t)__cvta_generic_to_shared(
            smem + s * STAGE_ELEMS + (wm + ((seg & 1) << 3) + lr) * AST + ((seg >> 1) << 3));
        bBase[s] = (uint32_t)__cvta_generic_to_shared(
            smem + s * STAGE_ELEMS + A_ELEMS + (wn + ((seg >> 1) << 3) + lr) * AST + ((seg & 1) << 3));
    }

    auto LDT = [&](int t) {
        const int ko = t * TK;
        __half* as = smem + (t % ST) * STAGE_ELEMS;
        __half* bs = as + A_ELEMS;
#pragma unroll
        for (int i = 0; i < 4; i++) {
            const int r = lrow + (i << 5);
            const void* sa = (const void*)(A + (size_t)(row0 + r) * lda + ko + lcol);
            uint32_t da = (uint32_t)__cvta_generic_to_shared(&as[r * AST + lcol]);
            asm volatile("cp.async.cg.shared.global [%0], [%1], 16;" :: "r"(da), "l"(sa));
            const void* sb = (const void*)(B + (size_t)(col0 + r) * ldb + ko + lcol);
            uint32_t db = (uint32_t)__cvta_generic_to_shared(&bs[r * AST + lcol]);
            asm volatile("cp.async.cg.shared.global [%0], [%1], 16;" :: "r"(db), "l"(sb));
        }
        asm volatile("cp.async.commit_group;" ::: "memory");
    };

    // Prologue: fill all 3 stages, arm k0 fragments of tile 0.
    LDT(0); LDT(1); LDT(2);
    asm volatile("cp.async.wait_group 2;" ::: "memory");
    __syncthreads();

    uint32_t af[2][4][4], bf[2][2][4];
#pragma unroll
    for (int mi = 0; mi < 4; mi++)
        LDSM_X4(af[0][mi][0], af[0][mi][1], af[0][mi][2], af[0][mi][3],
                aBase[0] + mi * (16 * AST * 2));
#pragma unroll
    for (int n2 = 0; n2 < 2; n2++)
        LDSM_X4(bf[0][n2][0], bf[0][n2][1], bf[0][n2][2], bf[0][n2][3],
                bBase[0] + n2 * (16 * AST * 2));

    for (int t = 0; t < ntiles; t++) {
        const int st = t % ST;
        const uint32_t ab = aBase[st], bb = bBase[st];

        // k-steps 0..2: prefetch next k-step fragments, mma current
#pragma unroll
        for (int kk = 0; kk < 3; kk++) {
            const int cur = kk & 1, nxt = cur ^ 1;
            const uint32_t ak = ab + (kk + 1) * 32;
            const uint32_t bk = bb + (kk + 1) * 32;
#pragma unroll
            for (int mi = 0; mi < 4; mi++)
                LDSM_X4(af[nxt][mi][0], af[nxt][mi][1], af[nxt][mi][2], af[nxt][mi][3],
                        ak + mi * (16 * AST * 2));
#pragma unroll
            for (int n2 = 0; n2 < 2; n2++)
                LDSM_X4(bf[nxt][n2][0], bf[nxt][n2][1], bf[nxt][n2][2], bf[nxt][n2][3],
                        bk + n2 * (16 * AST * 2));
#pragma unroll
            for (int mi = 0; mi < 4; mi++)
#pragma unroll
                for (int ni = 0; ni < 4; ni++)
                    MMA16816(acc[mi][ni], af[cur][mi],
                             bf[cur][ni >> 1][(ni & 1) << 1],
                             bf[cur][ni >> 1][((ni & 1) << 1) + 1]);
        }

        // k-step 3: publish stage t+1, preload its k0 fragments, then mma k3.
        if (t + 1 < ntiles) {
            if (t + 3 <= ntiles) { asm volatile("cp.async.wait_group 1;" ::: "memory"); }
            else                 { asm volatile("cp.async.wait_group 0;" ::: "memory"); }
            __syncthreads();
            const int sn = (t + 1) % ST;
#pragma unroll
            for (int mi = 0; mi < 4; mi++)
                LDSM_X4(af[0][mi][0], af[0][mi][1], af[0][mi][2], af[0][mi][3],
                        aBase[sn] + mi * (16 * AST * 2));
#pragma unroll
            for (int n2 = 0; n2 < 2; n2++)
                LDSM_X4(bf[0][n2][0], bf[0][n2][1], bf[0][n2][2], bf[0][n2][3],
                        bBase[sn] + n2 * (16 * AST * 2));
        }
#pragma unroll
        for (int mi = 0; mi < 4; mi++)
#pragma unroll
            for (int ni = 0; ni < 4; ni++)
                MMA16816(acc[mi][ni], af[1][mi],
                         bf[1][ni >> 1][(ni & 1) << 1],
                         bf[1][ni >> 1][((ni & 1) << 1) + 1]);

        if (t + 3 < ntiles) LDT(t + 3);
    }
    __syncthreads();
}

// ---------------------------------------------------------------------------
// Kernel: Q/K projections (z = 0/1), fp16 K=1024, row-major epilogue.
// ---------------------------------------------------------------------------
__global__ __launch_bounds__(256, 2) void proj_qk_kernel(
    const float* __restrict__ bq, const float* __restrict__ bk)
{
    const int z = blockIdx.z;
    const __half* W   = (z == 0) ? g_wq : g_wk;
    const float* bias = (z == 0) ? bq   : bk;
    const int row0 = blockIdx.y * TM, col0 = blockIdx.x * TN;

    float acc[4][4][4];
#pragma unroll
    for (int i = 0; i < 4; i++)
#pragma unroll
        for (int j = 0; j < 4; j++)
#pragma unroll
            for (int q = 0; q < 4; q++) acc[i][j][q] = 0.f;

    gemm_core(g_xh, row0, DD, W, col0, DD, DD / TK, acc);

    const int lane = threadIdx.x & 31, warp = threadIdx.x >> 5;
    const int wm = (warp & 1) << 6, wn = (warp >> 1) << 5;
    const int g = lane >> 2, tig = lane & 3;
    __half* base = (z == 0) ? g_qs : g_ks;

#pragma unroll
    for (int mi = 0; mi < 4; mi++)
#pragma unroll
        for (int ni = 0; ni < 4; ni++) {
            const int n = col0 + wn + (ni << 3) + (tig << 1);
            const float b0 = bias[n], b1 = bias[n + 1];
#pragma unroll
            for (int rr = 0; rr < 2; rr++) {
                const int m = row0 + wm + (mi << 4) + g + rr * 8;
                __half2 th;
                th.x = __float2half(acc[mi][ni][rr * 2 + 0] + b0);
                th.y = __float2half(acc[mi][ni][rr * 2 + 1] + b1);
                *(__half2*)(base + (size_t)m * DD + n) = th;
            }
        }
}

// ---------------------------------------------------------------------------
// Kernel: V projection, fp16 K=1024; smem-staged transpose epilogue ->
// coalesced half2 row writes into g_vt.  Runs on the forked stream.
// ---------------------------------------------------------------------------
#define TST 136   // transpose smem stride (halfs)

__global__ __launch_bounds__(256, 2) void proj_v_kernel(const float* __restrict__ bv)
{
    extern __shared__ __align__(16) __half smem[];
    const int row0 = blockIdx.y * TM, col0 = blockIdx.x * TN;

    float acc[4][4][4];
#pragma unroll
    for (int i = 0; i < 4; i++)
#pragma unroll
        for (int j = 0; j < 4; j++)
#pragma unroll
            for (int q = 0; q < 4; q++) acc[i][j][q] = 0.f;

    gemm_core(g_xh, row0, DD, g_wv, col0, DD, DD / TK, acc);

    const int tid = threadIdx.x;
    const int lane = tid & 31, warp = tid >> 5;
    const int wm = (warp & 1) << 6, wn = (warp >> 1) << 5;
    const int g = lane >> 2, tig = lane & 3;

    __half* st = smem;     // gemm_core ended with __syncthreads: smem free
#pragma unroll
    for (int mi = 0; mi < 4; mi++)
#pragma unroll
        for (int ni = 0; ni < 4; ni++) {
            const int nl = wn + (ni << 3) + (tig << 1);
            const float b0 = bv[col0 + nl], b1 = bv[col0 + nl + 1];
#pragma unroll
            for (int rr = 0; rr < 2; rr++) {
                const int ml = wm + (mi << 4) + g + rr * 8;
                st[nl * TST + ml]       = __float2half(acc[mi][ni][rr * 2 + 0] + b0);
                st[(nl + 1) * TST + ml] = __float2half(acc[mi][ni][rr * 2 + 1] + b1);
            }
        }
    __syncthreads();
    const int b = row0 >> 11, s0 = row0 & (SS - 1);
#pragma unroll
    for (int rep = 0; rep < 32; rep++) {
        const int idx = rep * 256 + tid;     // 0..8191 half2 slots
        const int d = idx >> 6;              // 0..127 (n_local)
        const int c = (idx & 63) << 1;       // 0..126 (m_local, even)
        __half2 v = *(__half2*)&st[d * TST + c];
        *(__half2*)&g_vt[((size_t)b * DD + col0 + d) * SS + s0 + c] = v;
    }
}

// ---------------------------------------------------------------------------
// Kernel: scores = Q K^T / sqrt(D), fp16 K=1024.  Compact triangular grid:
// blockIdx.x in [0,136) decodes to (by, bx) with bx <= by.
// ---------------------------------------------------------------------------
__global__ __launch_bounds__(256, 2) void scores_kernel()
{
    const int t = blockIdx.x, b = blockIdx.z;
    int by = (int)((sqrtf(8.f * t + 1.f) - 1.f) * 0.5f);
    while ((by + 1) * (by + 2) / 2 <= t) by++;
    while (by * (by + 1) / 2 > t) by--;
    const int bx = t - by * (by + 1) / 2;

    const __half* A  = g_qs + (size_t)b * SS * DD;
    const __half* Bp = g_ks + (size_t)b * SS * DD;
    const int row0 = by * TM, col0 = bx * TN;

    float acc[4][4][4];
#pragma unroll
    for (int i = 0; i < 4; i++)
#pragma unroll
        for (int j = 0; j < 4; j++)
#pragma unroll
            for (int q = 0; q < 4; q++) acc[i][j][q] = 0.f;

    gemm_core(A, row0, DD, Bp, col0, DD, DD / TK, acc);

    float* C = g_sc + (size_t)b * SS * SS;
    const int lane = threadIdx.x & 31, warp = threadIdx.x >> 5;
    const int wm = (warp & 1) << 6, wn = (warp >> 1) << 5;
    const int g = lane >> 2, tig = lane & 3;

#pragma unroll
    for (int mi = 0; mi < 4; mi++)
#pragma unroll
        for (int ni = 0; ni < 4; ni++) {
            const int n = col0 + wn + (ni << 3) + (tig << 1);
#pragma unroll
            for (int rr = 0; rr < 2; rr++) {
                const int m = row0 + wm + (mi << 4) + g + rr * 8;
                float2 v;
                v.x = acc[mi][ni][rr * 2 + 0] * 0.03125f;
                v.y = acc[mi][ni][rr * 2 + 1] * 0.03125f;
                *(float2*)(C + (size_t)m * SS + n) = v;
            }
        }
}

// ---------------------------------------------------------------------------
// Kernel: causal row softmax, vectorized + causally predicated I/O.
// Reads only j < len; writes only up to the end of the diagonal 128-block
// (exactly the region pv reads; zeros preserved there).
// ---------------------------------------------------------------------------
__global__ __launch_bounds__(256) void softmax_kernel()
{
    const int row = blockIdx.x;
    const int b = row >> 11;
    const int i = row & (SS - 1);
    const float* p = g_sc + (size_t)b * SS * SS + (size_t)i * SS;
    __half* o = g_ps + (size_t)b * SS * SS + (size_t)i * SS;
    const int len = i + 1;
    const int wlim = ((i >> 7) + 1) << 7;  // write limit = diagonal block end
    const int tid = threadIdx.x;
    const int lane = tid & 31, wid = tid >> 5;
    __shared__ float red[8];

    const int jb[2] = { tid * 4, 1024 + tid * 4 };
    float xv[8];
#pragma unroll
    for (int gr = 0; gr < 2; gr++) {
        float4 q = (jb[gr] < len) ? ((const float4*)p)[tid + gr * 256]
                                  : make_float4(0.f, 0.f, 0.f, 0.f);
        *(float4*)&xv[gr * 4] = q;
    }

    float m = __int_as_float(0xff800000);
#pragma unroll
    for (int gr = 0; gr < 2; gr++)
#pragma unroll
        for (int e = 0; e < 4; e++)
            if (jb[gr] + e < len) m = fmaxf(m, xv[gr * 4 + e]);
#pragma unroll
    for (int off = 16; off; off >>= 1) m = fmaxf(m, __shfl_xor_sync(0xffffffffu, m, off));
    if (lane == 0) red[wid] = m;
    __syncthreads();
    if (tid == 0) {
        float mm = red[0];
#pragma unroll
        for (int w = 1; w < 8; w++) mm = fmaxf(mm, red[w]);
        red[0] = mm;
    }
    __syncthreads();
    m = red[0];
    __syncthreads();

    float s = 0.f;
    float ev[8];
#pragma unroll
    for (int gr = 0; gr < 2; gr++)
#pragma unroll
        for (int e = 0; e < 4; e++) {
            int k = gr * 4 + e;
            ev[k] = (jb[gr] + e < len) ? __expf(xv[k] - m) : 0.f;
            s += ev[k];
        }
#pragma unroll
    for (int off = 16; off; off >>= 1) s += __shfl_xor_sync(0xffffffffu, s, off);
    if (lane == 0) red[wid] = s;
    __syncthreads();
    if (tid == 0) {
        float ss = 0.f;
#pragma unroll
        for (int w = 0; w < 8; w++) ss += red[w];
        red[0] = ss;
    }
    __syncthreads();
    const float inv = 1.f / red[0];

    __half2* o2 = (__half2*)o;
#pragma unroll
    for (int gr = 0; gr < 2; gr++) {
        if (jb[gr] < wlim) {
            __half2 h0, h1;
            h0.x = __float2half(ev[gr * 4 + 0] * inv);
            h0.y = __float2half(ev[gr * 4 + 1] * inv);
            h1.x = __float2half(ev[gr * 4 + 2] * inv);
            h1.y = __float2half(ev[gr * 4 + 3] * inv);
            o2[gr * 512 + tid * 2]     = h0;
            o2[gr * 512 + tid * 2 + 1] = h1;
        }
    }
}

// ---------------------------------------------------------------------------
// Kernel: out = P V, fp16, K capped at the diagonal; longest rows first.
// ---------------------------------------------------------------------------
__global__ __launch_bounds__(256, 2) void pv_kernel(float* __restrict__ out)
{
    const int bx = blockIdx.x, by = 15 - blockIdx.y, b = blockIdx.z;
    const __half* A  = g_ps + (size_t)b * SS * SS;
    const __half* Bp = g_vt + (size_t)b * DD * SS;
    const int row0 = by * TM, col0 = bx * TN;
    const int ntiles = (row0 + TM) / TK;   // causal cap (>= 2)

    float acc[4][4][4];
#pragma unroll
    for (int i = 0; i < 4; i++)
#pragma unroll
        for (int j = 0; j < 4; j++)
#pragma unroll
            for (int q = 0; q < 4; q++) acc[i][j][q] = 0.f;

    gemm_core(A, row0, SS, Bp, col0, SS, ntiles, acc);

    float* C = out + (size_t)b * SS * DD;
    const int lane = threadIdx.x & 31, warp = threadIdx.x >> 5;
    const int wm = (warp & 1) << 6, wn = (warp >> 1) << 5;
    const int g = lane >> 2, tig = lane & 3;

#pragma unroll
    for (int mi = 0; mi < 4; mi++)
#pragma unroll
        for (int ni = 0; ni < 4; ni++) {
            const int n = col0 + wn + (ni << 3) + (tig << 1);
#pragma unroll
            for (int rr = 0; rr < 2; rr++) {
                const int m = row0 + wm + (mi << 4) + g + rr * 8;
                float2 v;
                v.x = acc[mi][ni][rr * 2 + 0];
                v.y = acc[mi][ni][rr * 2 + 1];
                *(float2*)(C + (size_t)m * DD + n) = v;
            }
        }
}

// ---------------------------------------------------------------------------
extern "C" void kernel_launch(void* const* d_in, const int* in_sizes, int n_in,
                              void* d_out, int out_size)
{
    const float* x  = (const float*)d_in[0];
    const float* Wq = (const float*)d_in[1];
    const float* bq = (const float*)d_in[2];
    const float* Wk = (const float*)d_in[3];
    const float* bk = (const float*)d_in[4];
    const float* Wv = (const float*)d_in[5];
    const float* bv = (const float*)d_in[6];
    float* out = (float*)d_out;

    // One-time setup (first call = correctness run, outside graph capture).
    static cudaStream_t s2 = nullptr;
    static cudaEvent_t evFork = nullptr, evJoin = nullptr;
    if (!s2) {
        cudaStreamCreateWithFlags(&s2, cudaStreamNonBlocking);
        cudaEventCreateWithFlags(&evFork, cudaEventDisableTiming);
        cudaEventCreateWithFlags(&evJoin, cudaEventDisableTiming);
        cudaFuncSetAttribute(proj_qk_kernel, cudaFuncAttributeMaxDynamicSharedMemorySize, DYN_BYTES);
        cudaFuncSetAttribute(proj_v_kernel,  cudaFuncAttributeMaxDynamicSharedMemorySize, DYN_BYTES);
        cudaFuncSetAttribute(scores_kernel,  cudaFuncAttributeMaxDynamicSharedMemorySize, DYN_BYTES);
        cudaFuncSetAttribute(pv_kernel,      cudaFuncAttributeMaxDynamicSharedMemorySize, DYN_BYTES);
    }

    conv_x_kernel<<<(MM * DD / 2) / 256, 256>>>(x);
    conv_w_kernel<<<dim3((DD * DD / 2) / 256, 1, 3), 256>>>(Wq, Wk, Wv);

    // Fork: V projection on s2, QK->scores->softmax on the main stream.
    cudaEventRecord(evFork, 0);
    cudaStreamWaitEvent(s2, evFork, 0);
    proj_v_kernel<<<dim3(DD / TN, MM / TM), 256, DYN_BYTES, s2>>>(bv);
    cudaEventRecord(evJoin, s2);

    proj_qk_kernel<<<dim3(DD / TN, MM / TM, 2), 256, DYN_BYTES>>>(bq, bk);
    scores_kernel<<<dim3(136, 1, BB), 256, DYN_BYTES>>>();
    softmax_kernel<<<BB * SS, 256>>>();

    // Join: pv needs both softmax (main) and V (s2).
    cudaStreamWaitEvent(0, evJoin, 0);
    pv_kernel<<<dim3(DD / TN, SS / TM, BB), 256, DYN_BYTES>>>(out);
}